// round 3
// baseline (speedup 1.0000x reference)
#include <cuda_runtime.h>
#include <math.h>
#include <stddef.h>

// Problem constants
#define BATCH   1024
#define EMBED   16
#define S_MAX   16641
#define D_IN    16657          // S_MAX + EMBED
#define H4      1024           // 4*HIDDEN
#define H2      512
#define H1      256
#define NEXP    7
#define KCHUNK  2048
#define NSPLIT  9              // ceil(16641/2048)

__constant__ int c_sizes[NEXP] = {9, 25, 81, 289, 1089, 4225, 16641};

// -------- device scratch (static; no allocations allowed) --------
__device__ int   g_cnt[NEXP];
__device__ int   g_off[NEXP + 1];
__device__ int   g_idx[NEXP * BATCH];     // per-expert batch-index lists
__device__ int   g_rowb[BATCH];           // compact row -> original batch index
__device__ int   g_rowo[BATCH];           // compact row -> expert
__device__ float g_hpart[NSPLIT][BATCH][H4];  // split-K partials (36 MB)
__device__ float g_h [BATCH * H4];
__device__ float g_z1[BATCH * H2];
__device__ float g_z2[BATCH * H1];

// ---------------------------------------------------------------
// 1) Bucket rows by expert; build compact row order + offsets.
//    (Atomic order is nondeterministic but per-row results are
//     bitwise identical and scattered back by original index.)
// ---------------------------------------------------------------
__global__ void bucket_kernel(const int* __restrict__ orders)
{
    __shared__ int s_cnt[NEXP];
    __shared__ int s_off[NEXP];
    int b = threadIdx.x;
    if (b < NEXP) s_cnt[b] = 0;
    __syncthreads();
    int o   = orders[b];
    int pos = atomicAdd(&s_cnt[o], 1);
    __syncthreads();
    if (b == 0) {
        int a = 0;
        for (int i = 0; i < NEXP; i++) {
            s_off[i] = a; g_cnt[i] = s_cnt[i]; g_off[i] = a; a += s_cnt[i];
        }
        g_off[NEXP] = a;
    }
    __syncthreads();
    g_idx[o * BATCH + pos] = b;
    int row = s_off[o] + pos;
    g_rowb[row] = b;
    g_rowo[row] = o;
}

// ---------------------------------------------------------------
// 2) Layer 1 main GEMM, grouped by expert, split-K.
//    grid = (8 n-tiles, 16 m-tiles, 7 experts * 9 k-splits)
//    block tile: 64 (M) x 128 (N), KB=32, 256 threads, 4x8/thread.
// ---------------------------------------------------------------
__global__ __launch_bounds__(256, 2)
void layer1_kernel(const float* __restrict__ mazes,
                   const float* __restrict__ W_in)
{
    const int o = blockIdx.z / NSPLIT;
    const int c = blockIdx.z % NSPLIT;
    const int n_o = g_cnt[o];
    const int m0  = blockIdx.y * 64;
    if (m0 >= n_o) return;
    const int s    = c_sizes[o];
    const int kbeg = c * KCHUNK;
    if (kbeg >= s) return;
    const int kend = min(kbeg + KCHUNK, s);
    const int n0   = blockIdx.x * 128;

    __shared__ float Xs[32][68];     // [k][m], padded
    __shared__ float Ws[32][128];    // [k][n]
    __shared__ int   sridx[64];

    const int tid = threadIdx.x;
    if (tid < 64) {
        int m = m0 + tid;
        sridx[tid] = (m < n_o) ? g_idx[o * BATCH + m] : -1;
    }
    __syncthreads();

    const int tx = tid & 15;     // 16 col-groups of 8
    const int ty = tid >> 4;     // 16 row-groups of 4
    float acc[4][8];
#pragma unroll
    for (int i = 0; i < 4; i++)
#pragma unroll
        for (int j = 0; j < 8; j++) acc[i][j] = 0.f;

    const int xm = tid >> 2;           // 64 rows
    const int xk = (tid & 3) * 8;      // 4 threads * 8 k each
    const int  ridx  = sridx[xm];
    const bool xvalid = (ridx >= 0);
    const float* xrow = xvalid ? (mazes + (size_t)ridx * S_MAX) : mazes;

    const float* wbase = W_in + (size_t)o * D_IN * H4 + n0;

    for (int k0 = kbeg; k0 < kend; k0 += 32) {
        // X tile: 64 rows x 32 k (gathered rows; coalesced along k)
#pragma unroll
        for (int i = 0; i < 8; i++) {
            int k = k0 + xk + i;
            float v = 0.f;
            if (xvalid && k < kend) v = xrow[k];
            Xs[xk + i][xm] = v;
        }
        // W tile: 32 k x 128 n via float4 (1024 float4 = 256 thr * 4)
#pragma unroll
        for (int i = 0; i < 4; i++) {
            int idx = tid + i * 256;
            int kk  = idx >> 5;
            int j4  = (idx & 31) * 4;
            float4 v = make_float4(0.f, 0.f, 0.f, 0.f);
            int k = k0 + kk;
            if (k < kend) v = *(const float4*)(wbase + (size_t)k * H4 + j4);
            *(float4*)&Ws[kk][j4] = v;
        }
        __syncthreads();
#pragma unroll
        for (int kk = 0; kk < 32; kk++) {
            float a[4], w[8];
#pragma unroll
            for (int i = 0; i < 4; i++) a[i] = Xs[kk][ty * 4 + i];
#pragma unroll
            for (int j = 0; j < 8; j++) w[j] = Ws[kk][tx * 8 + j];
#pragma unroll
            for (int i = 0; i < 4; i++)
#pragma unroll
                for (int j = 0; j < 8; j++) acc[i][j] += a[i] * w[j];
        }
        __syncthreads();
    }

    const int roff = g_off[o] + m0;
#pragma unroll
    for (int i = 0; i < 4; i++) {
        int m = ty * 4 + i;
        if (m0 + m < n_o) {
            float* dst = &g_hpart[c][roff + m][n0 + tx * 8];
            *(float4*)(dst)     = make_float4(acc[i][0], acc[i][1], acc[i][2], acc[i][3]);
            *(float4*)(dst + 4) = make_float4(acc[i][4], acc[i][5], acc[i][6], acc[i][7]);
        }
    }
}

// ---------------------------------------------------------------
// 3) Layer-1 epilogue: fixed-order split reduction + embed rows
//    + bias + leaky_relu.  One block per compact row.
// ---------------------------------------------------------------
__global__ void l1_epilogue(const float* __restrict__ embed,
                            const float* __restrict__ W_in,
                            const float* __restrict__ b_in)
{
    const int r = blockIdx.x;
    const int o = g_rowo[r];
    const int ns = (c_sizes[o] + KCHUNK - 1) / KCHUNK;
    __shared__ float se[EMBED];
    if (threadIdx.x < EMBED) se[threadIdx.x] = embed[o * EMBED + threadIdx.x];
    __syncthreads();
    const float* wE = W_in + ((size_t)o * D_IN + S_MAX) * H4;
    for (int j = threadIdx.x; j < H4; j += blockDim.x) {
        float v = b_in[o * H4 + j];
        for (int c = 0; c < ns; c++) v += g_hpart[c][r][j];
#pragma unroll
        for (int e = 0; e < EMBED; e++) v += se[e] * wE[(size_t)e * H4 + j];
        g_h[(size_t)r * H4 + j] = (v > 0.f) ? v : 0.2f * v;
    }
}

// ---------------------------------------------------------------
// 4) Shared 1024->512 and 512->256 GEMMs with leaky epilogue.
//    64x64 tile, KB=32, 256 threads, 4x4/thread.
//    sel=0: g_h @ W1 -> g_z1 ; sel=1: g_z1 @ W2 -> g_z2
// ---------------------------------------------------------------
__global__ __launch_bounds__(256)
void gemm_leaky(const float* __restrict__ B,
                const float* __restrict__ bias,
                int K, int N, int sel)
{
    const float* A = (sel == 0) ? g_h  : g_z1;
    float*       C = (sel == 0) ? g_z1 : g_z2;

    __shared__ float As[32][68];
    __shared__ float Bs[32][64];
    const int m0 = blockIdx.y * 64, n0 = blockIdx.x * 64;
    const int tid = threadIdx.x;
    const int tx = tid & 15, ty = tid >> 4;
    float acc[4][4] = {};

    const int am = tid >> 2;
    const int ak = (tid & 3) * 8;
    const float* arow = A + (size_t)(m0 + am) * K;

    for (int k0 = 0; k0 < K; k0 += 32) {
#pragma unroll
        for (int i = 0; i < 8; i += 4) {
            float4 v = *(const float4*)(arow + k0 + ak + i);
            As[ak + i    ][am] = v.x;
            As[ak + i + 1][am] = v.y;
            As[ak + i + 2][am] = v.z;
            As[ak + i + 3][am] = v.w;
        }
#pragma unroll
        for (int i = 0; i < 2; i++) {
            int idx = tid + i * 256;
            int kk  = idx >> 4;
            int j4  = (idx & 15) * 4;
            *(float4*)&Bs[kk][j4] =
                *(const float4*)(B + (size_t)(k0 + kk) * N + n0 + j4);
        }
        __syncthreads();
#pragma unroll
        for (int kk = 0; kk < 32; kk++) {
            float a[4], w[4];
#pragma unroll
            for (int i = 0; i < 4; i++) a[i] = As[kk][ty * 4 + i];
#pragma unroll
            for (int j = 0; j < 4; j++) w[j] = Bs[kk][tx * 4 + j];
#pragma unroll
            for (int i = 0; i < 4; i++)
#pragma unroll
                for (int j = 0; j < 4; j++) acc[i][j] += a[i] * w[j];
        }
        __syncthreads();
    }

#pragma unroll
    for (int i = 0; i < 4; i++) {
        int m = m0 + ty * 4 + i;
#pragma unroll
        for (int j = 0; j < 4; j++) {
            int n = n0 + tx * 4 + j;
            float v = acc[i][j] + bias[n];
            C[(size_t)m * N + n] = (v > 0.f) ? v : 0.2f * v;
        }
    }
}

// ---------------------------------------------------------------
// 5) Final 256->1 GEMV + sigmoid, scattered to original batch order.
//    8 warps/block, one warp per row.
// ---------------------------------------------------------------
__global__ void l4_kernel(const float* __restrict__ W3,
                          const float* __restrict__ b3,
                          float* __restrict__ out)
{
    const int warp = threadIdx.x >> 5;
    const int lane = threadIdx.x & 31;
    const int r = blockIdx.x * 8 + warp;
    const float* z = g_z2 + (size_t)r * H1;
    float p = 0.f;
#pragma unroll
    for (int l = 0; l < 8; l++) {
        int j = lane + l * 32;
        p += z[j] * W3[j];
    }
#pragma unroll
    for (int d = 16; d; d >>= 1) p += __shfl_xor_sync(0xffffffffu, p, d);
    if (lane == 0) {
        float x = p + b3[0];
        out[g_rowb[r]] = 1.f / (1.f + expf(-x));
    }
}

// ---------------------------------------------------------------
extern "C" void kernel_launch(void* const* d_in, const int* in_sizes, int n_in,
                              void* d_out, int out_size)
{
    const float* mazes  = (const float*)d_in[0];
    const int*   orders = (const int*)  d_in[1];
    const float* embed  = (const float*)d_in[2];
    const float* W_in   = (const float*)d_in[3];
    const float* b_in   = (const float*)d_in[4];
    const float* W1     = (const float*)d_in[5];
    const float* b1     = (const float*)d_in[6];
    const float* W2     = (const float*)d_in[7];
    const float* b2     = (const float*)d_in[8];
    const float* W3     = (const float*)d_in[9];
    const float* b3     = (const float*)d_in[10];
    float* out = (float*)d_out;

    bucket_kernel<<<1, BATCH>>>(orders);
    layer1_kernel<<<dim3(H4 / 128, BATCH / 64, NEXP * NSPLIT), 256>>>(mazes, W_in);
    l1_epilogue<<<BATCH, 256>>>(embed, W_in, b_in);
    gemm_leaky<<<dim3(H2 / 64, BATCH / 64), 256>>>(W1, b1, H4, H2, 0);
    gemm_leaky<<<dim3(H1 / 64, BATCH / 64), 256>>>(W2, b2, H2, H1, 1);
    l4_kernel<<<BATCH / 8, 256>>>(W3, b3, out);
}

// round 5
// speedup vs baseline: 1.0085x; 1.0085x over previous
#include <cuda_runtime.h>
#include <math.h>
#include <stdint.h>
#include <stddef.h>

// ---------------- problem constants ----------------
#define BATCH   1024
#define EMBED   16
#define S_MAX   16641
#define D_IN    16657
#define H4      1024
#define H2      512
#define H1      256
#define NEXP    7
#define KCHUNK  2048
#define NSPLIT_MAX 9
#define NZ      17

__constant__ int c_sizes[NEXP]  = {9, 25, 81, 289, 1089, 4225, 16641};
__constant__ int c_nsplit[NEXP] = {1, 1, 1, 1, 1, 3, 9};
__constant__ int c_zo[NZ] = {0,1,2,3,4,5,5,5,6,6,6,6,6,6,6,6,6};
__constant__ int c_zc[NZ] = {0,0,0,0,0,0,1,2,0,1,2,3,4,5,6,7,8};

// ---------------- device scratch (static) ----------------
__device__ int   g_cnt[NEXP];
__device__ int   g_off[NEXP + 1];
__device__ int   g_idx[NEXP * BATCH];
__device__ int   g_rowb[BATCH];
__device__ int   g_rowo[BATCH];
__device__ float g_hpart[NSPLIT_MAX][BATCH][H4];   // split-K partials
__device__ float g_h [BATCH * H4];
__device__ float g_z1[BATCH * H2];
__device__ float g_z2[BATCH * H1];

// ---------------- helpers ----------------
__device__ __forceinline__ uint32_t f2tf32(float f) {
    uint32_t u;
    asm("cvt.rna.tf32.f32 %0, %1;" : "=r"(u) : "f"(f));
    return u;
}
__device__ __forceinline__ void mma_tf32(float* c, const uint32_t* a, const uint32_t* b) {
    asm volatile(
        "mma.sync.aligned.m16n8k8.row.col.f32.tf32.tf32.f32 "
        "{%0,%1,%2,%3}, {%4,%5,%6,%7}, {%8,%9}, {%0,%1,%2,%3};"
        : "+f"(c[0]), "+f"(c[1]), "+f"(c[2]), "+f"(c[3])
        : "r"(a[0]), "r"(a[1]), "r"(a[2]), "r"(a[3]), "r"(b[0]), "r"(b[1]));
}

// tile geometry
#define BM 128
#define BN 128
#define BK 32
#define A_PAD 36     // floats per A row (32 + 4)
#define B_PAD 132    // floats per B row (128 + 4)

// ---------------------------------------------------------------
// bucket rows by expert
// ---------------------------------------------------------------
__global__ void bucket_kernel(const int* __restrict__ orders)
{
    __shared__ int s_cnt[NEXP];
    __shared__ int s_off[NEXP];
    int b = threadIdx.x;
    if (b < NEXP) s_cnt[b] = 0;
    __syncthreads();
    int o = orders[b];
    int pos = atomicAdd(&s_cnt[o], 1);
    __syncthreads();
    if (b == 0) {
        int a = 0;
        for (int i = 0; i < NEXP; i++) { s_off[i] = a; g_cnt[i] = s_cnt[i]; g_off[i] = a; a += s_cnt[i]; }
        g_off[NEXP] = a;
    }
    __syncthreads();
    g_idx[o * BATCH + pos] = b;
    int row = s_off[o] + pos;
    g_rowb[row] = b;
    g_rowo[row] = o;
}

// ---------------------------------------------------------------
// Layer-1 grouped tf32 mma.sync GEMM, split-K, embed folded in.
// grid = (8 n-tiles, 8 m-tiles, 17 z), 256 threads (8 warps 4x2).
// ---------------------------------------------------------------
__global__ __launch_bounds__(256, 2)
void layer1_mma(const float* __restrict__ mazes,
                const float* __restrict__ W_in,
                const float* __restrict__ embed)
{
    const int z = blockIdx.z;
    const int o = c_zo[z];
    const int c = c_zc[z];
    const int cnt = g_cnt[o];
    const int m0 = blockIdx.y * BM;
    if (m0 >= cnt) return;
    const int s    = c_sizes[o];
    const int Ktot = s + EMBED;
    const int kbeg = c * KCHUNK;
    if (kbeg >= Ktot) return;
    const int kend = min(kbeg + KCHUNK, Ktot);
    const int n0   = blockIdx.x * BN;

    __shared__ uint32_t As[BM * A_PAD];   // [m][k] tf32 bits
    __shared__ uint32_t Bs[BK * B_PAD];   // [k][n] tf32 bits

    const int tid  = threadIdx.x;
    const int wid  = tid >> 5;
    const int lane = tid & 31;
    const int gid  = lane >> 2;     // group id 0..7
    const int tig  = lane & 3;      // thread-in-group 0..3
    const int warp_m = (wid >> 1) * 32;
    const int warp_n = (wid & 1) * 64;

    // A fill coords: 2 threads per m row, 16 k each
    const int am = tid >> 1;
    const int ak = (tid & 1) * 16;
    const int gm = m0 + am;
    const int ridx = (gm < cnt) ? g_idx[o * BATCH + gm] : -1;
    const float* xrow = mazes + (size_t)((ridx >= 0) ? ridx : 0) * S_MAX;
    const float* eo   = embed + o * EMBED;
    // B fill coords: 32 threads per k-row span, each thread 4 cols x 4 rows
    const int bn  = (tid & 31) * 4;
    const int bk0 = tid >> 5;       // rows bk0, bk0+8, bk0+16, bk0+24
    const float* wexp = W_in + (size_t)o * D_IN * H4;

    float acc[2][8][4];
#pragma unroll
    for (int i = 0; i < 2; i++)
#pragma unroll
        for (int j = 0; j < 8; j++)
#pragma unroll
            for (int q = 0; q < 4; q++) acc[i][j][q] = 0.f;

    for (int k0 = kbeg; k0 < kend; k0 += BK) {
        // ---- A tile ----
#pragma unroll
        for (int i = 0; i < 16; i++) {
            int k = k0 + ak + i;
            float v = 0.f;
            if (ridx >= 0 && k < kend) v = (k < s) ? __ldg(xrow + k) : __ldg(eo + (k - s));
            As[am * A_PAD + ak + i] = f2tf32(v);
        }
        // ---- B tile (W is [k][n] row-major) ----
#pragma unroll
        for (int j = 0; j < 4; j++) {
            int kk = bk0 + j * 8;
            int k  = k0 + kk;
            uint4 u = make_uint4(0u, 0u, 0u, 0u);
            if (k < kend) {
                int wr = (k < s) ? k : (S_MAX + (k - s));
                float4 w4 = *(const float4*)(wexp + (size_t)wr * H4 + n0 + bn);
                u.x = f2tf32(w4.x); u.y = f2tf32(w4.y); u.z = f2tf32(w4.z); u.w = f2tf32(w4.w);
            }
            *(uint4*)&Bs[kk * B_PAD + bn] = u;
        }
        __syncthreads();

        // ---- compute ----
#pragma unroll
        for (int kf = 0; kf < 4; kf++) {
            uint32_t a[2][4];
#pragma unroll
            for (int mf = 0; mf < 2; mf++) {
                int r = warp_m + mf * 16 + gid;
                a[mf][0] = As[r * A_PAD + kf * 8 + tig];
                a[mf][1] = As[(r + 8) * A_PAD + kf * 8 + tig];
                a[mf][2] = As[r * A_PAD + kf * 8 + tig + 4];
                a[mf][3] = As[(r + 8) * A_PAD + kf * 8 + tig + 4];
            }
            uint32_t b[8][2];
#pragma unroll
            for (int nf = 0; nf < 8; nf++) {
                int col = warp_n + nf * 8 + gid;
                b[nf][0] = Bs[(kf * 8 + tig) * B_PAD + col];
                b[nf][1] = Bs[(kf * 8 + tig + 4) * B_PAD + col];
            }
#pragma unroll
            for (int mf = 0; mf < 2; mf++)
#pragma unroll
                for (int nf = 0; nf < 8; nf++)
                    mma_tf32(acc[mf][nf], a[mf], b[nf]);
        }
        __syncthreads();
    }

    // ---- writeback partials ----
    const int grow0 = g_off[o] + m0;
#pragma unroll
    for (int mf = 0; mf < 2; mf++) {
        int r0 = warp_m + mf * 16 + gid;
#pragma unroll
        for (int h = 0; h < 2; h++) {
            int r = r0 + h * 8;
            if (m0 + r < cnt) {
                float* dst = &g_hpart[c][grow0 + r][n0 + warp_n];
#pragma unroll
                for (int nf = 0; nf < 8; nf++) {
                    float2 v = make_float2(acc[mf][nf][h * 2], acc[mf][nf][h * 2 + 1]);
                    *(float2*)(dst + nf * 8 + tig * 2) = v;
                }
            }
        }
    }
}

// ---------------------------------------------------------------
// Layer-1 epilogue: fixed-order split reduction + bias + leaky
// ---------------------------------------------------------------
__global__ void l1_epilogue(const float* __restrict__ b_in)
{
    const int r  = blockIdx.x;
    const int o  = g_rowo[r];
    const int ns = c_nsplit[o];
    const int j  = threadIdx.x * 4;
    float4 v = *(const float4*)(b_in + (size_t)o * H4 + j);
    for (int cc = 0; cc < ns; cc++) {
        float4 p = *(const float4*)(&g_hpart[cc][r][j]);
        v.x += p.x; v.y += p.y; v.z += p.z; v.w += p.w;
    }
    v.x = (v.x > 0.f) ? v.x : 0.2f * v.x;
    v.y = (v.y > 0.f) ? v.y : 0.2f * v.y;
    v.z = (v.z > 0.f) ? v.z : 0.2f * v.z;
    v.w = (v.w > 0.f) ? v.w : 0.2f * v.w;
    *(float4*)(g_h + (size_t)r * H4 + j) = v;
}

// ---------------------------------------------------------------
// Dense tf32 mma.sync GEMM + bias + leaky.
// sel=0: g_h[1024x1024] @ W1 -> g_z1 ; sel=1: g_z1[1024x512] @ W2 -> g_z2
// grid = (N/128, 8), 256 threads.
// ---------------------------------------------------------------
__global__ __launch_bounds__(256, 2)
void dense_mma(const float* __restrict__ B, const float* __restrict__ bias,
               int K, int N, int sel)
{
    const float* A = (sel == 0) ? g_h  : g_z1;
    float*       C = (sel == 0) ? g_z1 : g_z2;
    const int m0 = blockIdx.y * BM;
    const int n0 = blockIdx.x * BN;

    __shared__ uint32_t As[BM * A_PAD];
    __shared__ uint32_t Bs[BK * B_PAD];

    const int tid  = threadIdx.x;
    const int wid  = tid >> 5;
    const int lane = tid & 31;
    const int gid  = lane >> 2;
    const int tig  = lane & 3;
    const int warp_m = (wid >> 1) * 32;
    const int warp_n = (wid & 1) * 64;

    const int am = tid >> 1;
    const int ak = (tid & 1) * 16;
    const float* arow = A + (size_t)(m0 + am) * K;
    const int bn  = (tid & 31) * 4;
    const int bk0 = tid >> 5;

    float acc[2][8][4];
#pragma unroll
    for (int i = 0; i < 2; i++)
#pragma unroll
        for (int j = 0; j < 8; j++)
#pragma unroll
            for (int q = 0; q < 4; q++) acc[i][j][q] = 0.f;

    for (int k0 = 0; k0 < K; k0 += BK) {
#pragma unroll
        for (int i = 0; i < 16; i += 4) {
            float4 v = *(const float4*)(arow + k0 + ak + i);
            As[am * A_PAD + ak + i    ] = f2tf32(v.x);
            As[am * A_PAD + ak + i + 1] = f2tf32(v.y);
            As[am * A_PAD + ak + i + 2] = f2tf32(v.z);
            As[am * A_PAD + ak + i + 3] = f2tf32(v.w);
        }
#pragma unroll
        for (int j = 0; j < 4; j++) {
            int kk = bk0 + j * 8;
            float4 w4 = *(const float4*)(B + (size_t)(k0 + kk) * N + n0 + bn);
            uint4 u;
            u.x = f2tf32(w4.x); u.y = f2tf32(w4.y); u.z = f2tf32(w4.z); u.w = f2tf32(w4.w);
            *(uint4*)&Bs[kk * B_PAD + bn] = u;
        }
        __syncthreads();

#pragma unroll
        for (int kf = 0; kf < 4; kf++) {
            uint32_t a[2][4];
#pragma unroll
            for (int mf = 0; mf < 2; mf++) {
                int r = warp_m + mf * 16 + gid;
                a[mf][0] = As[r * A_PAD + kf * 8 + tig];
                a[mf][1] = As[(r + 8) * A_PAD + kf * 8 + tig];
                a[mf][2] = As[r * A_PAD + kf * 8 + tig + 4];
                a[mf][3] = As[(r + 8) * A_PAD + kf * 8 + tig + 4];
            }
            uint32_t b[8][2];
#pragma unroll
            for (int nf = 0; nf < 8; nf++) {
                int col = warp_n + nf * 8 + gid;
                b[nf][0] = Bs[(kf * 8 + tig) * B_PAD + col];
                b[nf][1] = Bs[(kf * 8 + tig + 4) * B_PAD + col];
            }
#pragma unroll
            for (int mf = 0; mf < 2; mf++)
#pragma unroll
                for (int nf = 0; nf < 8; nf++)
                    mma_tf32(acc[mf][nf], a[mf], b[nf]);
        }
        __syncthreads();
    }

#pragma unroll
    for (int mf = 0; mf < 2; mf++) {
        int r0 = warp_m + mf * 16 + gid;
#pragma unroll
        for (int h = 0; h < 2; h++) {
            int m = m0 + r0 + h * 8;
            float* dst = C + (size_t)m * N + n0 + warp_n;
            const float* bs = bias + n0 + warp_n;
#pragma unroll
            for (int nf = 0; nf < 8; nf++) {
                float x = acc[mf][nf][h * 2]     + __ldg(bs + nf * 8 + tig * 2);
                float y = acc[mf][nf][h * 2 + 1] + __ldg(bs + nf * 8 + tig * 2 + 1);
                x = (x > 0.f) ? x : 0.2f * x;
                y = (y > 0.f) ? y : 0.2f * y;
                *(float2*)(dst + nf * 8 + tig * 2) = make_float2(x, y);
            }
        }
    }
}

// ---------------------------------------------------------------
// Final 256->1 GEMV + sigmoid, scatter to original batch order.
// ---------------------------------------------------------------
__global__ void l4_kernel(const float* __restrict__ W3,
                          const float* __restrict__ b3,
                          float* __restrict__ out)
{
    const int warp = threadIdx.x >> 5;
    const int lane = threadIdx.x & 31;
    const int r = blockIdx.x * 8 + warp;
    const float* zv = g_z2 + (size_t)r * H1;
    float p = 0.f;
#pragma unroll
    for (int l = 0; l < 8; l++) p += zv[lane + l * 32] * W3[lane + l * 32];
#pragma unroll
    for (int d = 16; d; d >>= 1) p += __shfl_xor_sync(0xffffffffu, p, d);
    if (lane == 0) {
        float x = p + b3[0];
        out[g_rowb[r]] = 1.f / (1.f + expf(-x));
    }
}

// ---------------------------------------------------------------
extern "C" void kernel_launch(void* const* d_in, const int* in_sizes, int n_in,
                              void* d_out, int out_size)
{
    const float* mazes  = (const float*)d_in[0];
    const int*   orders = (const int*)  d_in[1];
    const float* embed  = (const float*)d_in[2];
    const float* W_in   = (const float*)d_in[3];
    const float* b_in   = (const float*)d_in[4];
    const float* W1     = (const float*)d_in[5];
    const float* b1     = (const float*)d_in[6];
    const float* W2     = (const float*)d_in[7];
    const float* b2     = (const float*)d_in[8];
    const float* W3     = (const float*)d_in[9];
    const float* b3     = (const float*)d_in[10];
    float* out = (float*)d_out;

    bucket_kernel<<<1, BATCH>>>(orders);
    layer1_mma<<<dim3(H4 / BN, BATCH / BM, NZ), 256>>>(mazes, W_in, embed);
    l1_epilogue<<<BATCH, 256>>>(b_in);
    dense_mma<<<dim3(H2 / BN, BATCH / BM), 256>>>(W1, b1, H4, H2, 0);
    dense_mma<<<dim3(H1 / BN, BATCH / BM), 256>>>(W2, b2, H2, H1, 1);
    l4_kernel<<<BATCH / 8, 256>>>(W3, b3, out);
}

// round 6
// speedup vs baseline: 1.6852x; 1.6710x over previous
#include <cuda_runtime.h>
#include <math.h>
#include <stdint.h>
#include <stddef.h>

// ---------------- problem constants ----------------
#define BATCH   1024
#define EMBED   16
#define S_MAX   16641
#define D_IN    16657
#define H4      1024
#define H2      512
#define H1      256
#define NEXP    7
#define KCHUNK  2048
#define NSPLIT_MAX 9
#define NZ      17

__constant__ int c_sizes[NEXP]  = {9, 25, 81, 289, 1089, 4225, 16641};
__constant__ int c_nsplit[NEXP] = {1, 1, 1, 1, 1, 3, 9};
__constant__ int c_zo[NZ] = {0,1,2,3,4,5,5,5,6,6,6,6,6,6,6,6,6};
__constant__ int c_zc[NZ] = {0,0,0,0,0,0,1,2,0,1,2,3,4,5,6,7,8};

// ---------------- device scratch (static) ----------------
__device__ int   g_cnt[NEXP];
__device__ int   g_off[NEXP + 1];
__device__ int   g_idx[NEXP * BATCH];
__device__ int   g_rowb[BATCH];
__device__ int   g_rowo[BATCH];
__device__ float g_hpart[NSPLIT_MAX][BATCH][H4];
__device__ float g_h [BATCH * H4];
__device__ float g_z1[BATCH * H2];
__device__ float g_z2[BATCH * H1];

// ---------------- helpers ----------------
__device__ __forceinline__ void mma_tf32(float* c, const uint32_t* a, const uint32_t* b) {
    asm volatile(
        "mma.sync.aligned.m16n8k8.row.col.f32.tf32.tf32.f32 "
        "{%0,%1,%2,%3}, {%4,%5,%6,%7}, {%8,%9}, {%0,%1,%2,%3};"
        : "+f"(c[0]), "+f"(c[1]), "+f"(c[2]), "+f"(c[3])
        : "r"(a[0]), "r"(a[1]), "r"(a[2]), "r"(a[3]), "r"(b[0]), "r"(b[1]));
}
__device__ __forceinline__ void cp4(uint32_t dst, const void* src, bool p) {
    asm volatile("cp.async.ca.shared.global [%0], [%1], 4, %2;"
                 :: "r"(dst), "l"(src), "r"(p ? 4 : 0) : "memory");
}
__device__ __forceinline__ void cp16(uint32_t dst, const void* src, bool p) {
    asm volatile("cp.async.cg.shared.global [%0], [%1], 16, %2;"
                 :: "r"(dst), "l"(src), "r"(p ? 16 : 0) : "memory");
}
#define CP_COMMIT() asm volatile("cp.async.commit_group;" ::: "memory")
#define CP_WAIT1()  asm volatile("cp.async.wait_group 1;" ::: "memory")
#define CP_WAIT0()  asm volatile("cp.async.wait_group 0;" ::: "memory")

// ---------------- tile geometry ----------------
#define BM 128
#define BN 128
#define BK 32
#define A_PAD 36                    // u32 per A row (16B-aligned pitch: 144B)
#define B_PAD 132                   // u32 per B row (528B pitch)
#define A_TILE (BM * A_PAD)         // 4608 u32
#define B_TILE (BK * B_PAD)         // 4224 u32
#define L1_SMEM ((2 * A_TILE + 2 * B_TILE) * 4)   // 70656 B

#define DM 64
#define DN 64
#define DB_PAD 68
#define DA_TILE (DM * A_PAD)        // 2304 u32
#define DB_TILE (BK * DB_PAD)       // 2176 u32

// ---------------------------------------------------------------
// bucket rows by expert
// ---------------------------------------------------------------
__global__ void bucket_kernel(const int* __restrict__ orders)
{
    __shared__ int s_cnt[NEXP];
    __shared__ int s_off[NEXP];
    int b = threadIdx.x;
    if (b < NEXP) s_cnt[b] = 0;
    __syncthreads();
    int o = orders[b];
    int pos = atomicAdd(&s_cnt[o], 1);
    __syncthreads();
    if (b == 0) {
        int a = 0;
        for (int i = 0; i < NEXP; i++) { s_off[i] = a; g_cnt[i] = s_cnt[i]; g_off[i] = a; a += s_cnt[i]; }
        g_off[NEXP] = a;
    }
    __syncthreads();
    g_idx[o * BATCH + pos] = b;
    int row = s_off[o] + pos;
    g_rowb[row] = b;
    g_rowo[row] = o;
}

// ---------------------------------------------------------------
// Layer-1 grouped tf32 GEMM, split-K, cp.async double-buffered.
// grid = (8 n-tiles, 8 m-tiles, 17 z), 256 threads (8 warps 4x2).
// ---------------------------------------------------------------
__global__ __launch_bounds__(256)
void layer1_mma(const float* __restrict__ mazes,
                const float* __restrict__ W_in,
                const float* __restrict__ embed)
{
    const int z = blockIdx.z;
    const int o = c_zo[z];
    const int c = c_zc[z];
    const int cnt = g_cnt[o];
    const int m0 = blockIdx.y * BM;
    if (m0 >= cnt) return;
    const int s    = c_sizes[o];
    const int Ktot = s + EMBED;
    const int kbeg = c * KCHUNK;
    if (kbeg >= Ktot) return;
    const int kend = min(kbeg + KCHUNK, Ktot);
    const int n0   = blockIdx.x * BN;

    extern __shared__ uint32_t sm[];
    uint32_t* AsBuf = sm;
    uint32_t* BsBuf = sm + 2 * A_TILE;
    const uint32_t smb  = (uint32_t)__cvta_generic_to_shared(sm);
    const uint32_t aOffB = smb;
    const uint32_t bOffB = smb + 2 * A_TILE * 4;

    __shared__ const float* srow[BM];

    const int tid  = threadIdx.x;
    const int wid  = tid >> 5;
    const int lane = tid & 31;
    const int gid  = lane >> 2;
    const int tig  = lane & 3;
    const int warp_m = (wid >> 1) * 32;
    const int warp_n = (wid & 1) * 64;

    if (tid < BM) {
        int gm = m0 + tid;
        int ridx = (gm < cnt) ? g_idx[o * BATCH + gm] : -1;
        srow[tid] = (ridx >= 0) ? (mazes + (size_t)ridx * S_MAX) : (const float*)0;
    }
    __syncthreads();

    const int am = tid >> 1;
    const int ak = (tid & 1) * 16;
    const float* eo   = embed + o * EMBED;
    const float* wexp = W_in + (size_t)o * D_IN * H4;

    float acc[2][8][4];
#pragma unroll
    for (int i = 0; i < 2; i++)
#pragma unroll
        for (int j = 0; j < 8; j++)
#pragma unroll
            for (int q = 0; q < 4; q++) acc[i][j][q] = 0.f;

    const int T = (kend - kbeg + BK - 1) / BK;

    // ---- load-issue (into buf t&1) ----
    auto issue = [&](int t) {
        const int k0  = kbeg + t * BK;
        const int buf = t & 1;
        const float* sr = srow[am];
        const bool pure = (k0 + BK <= s) && (k0 + BK <= kend);
        if (pure) {
            uint32_t dst = aOffB + (uint32_t)(buf * A_TILE + am * A_PAD + ak) * 4;
            const float* src = sr ? (sr + k0 + ak) : mazes;
            const bool p = (sr != 0);
#pragma unroll
            for (int i = 0; i < 16; i++) cp4(dst + i * 4, src + i, p);
        } else {
            uint32_t* As = AsBuf + buf * A_TILE;
#pragma unroll
            for (int i = 0; i < 16; i++) {
                int k = k0 + ak + i;
                float v = 0.f;
                if (sr && k < kend) v = (k < s) ? __ldg(sr + k) : __ldg(eo + (k - s));
                As[am * A_PAD + ak + i] = __float_as_uint(v);
            }
        }
#pragma unroll
        for (int j = 0; j < 4; j++) {
            int cch = tid + j * 256;
            int kk  = cch >> 5;
            int col = (cch & 31) * 4;
            int k   = k0 + kk;
            bool p  = (k < kend);
            int wr  = p ? ((k < s) ? k : (S_MAX + (k - s))) : 0;
            uint32_t dst = bOffB + (uint32_t)(buf * B_TILE + kk * B_PAD + col) * 4;
            cp16(dst, wexp + (size_t)wr * H4 + n0 + col, p);
        }
        CP_COMMIT();
    };

    issue(0);
    for (int t = 0; t < T; t++) {
        if (t + 1 < T) { issue(t + 1); CP_WAIT1(); }
        else           { CP_WAIT0(); }
        __syncthreads();

        const uint32_t* As = AsBuf + (t & 1) * A_TILE;
        const uint32_t* Bs = BsBuf + (t & 1) * B_TILE;
#pragma unroll
        for (int kf = 0; kf < 4; kf++) {
            uint32_t a[2][4];
#pragma unroll
            for (int mf = 0; mf < 2; mf++) {
                int r = warp_m + mf * 16 + gid;
                a[mf][0] = As[r * A_PAD + kf * 8 + tig];
                a[mf][1] = As[(r + 8) * A_PAD + kf * 8 + tig];
                a[mf][2] = As[r * A_PAD + kf * 8 + tig + 4];
                a[mf][3] = As[(r + 8) * A_PAD + kf * 8 + tig + 4];
            }
            uint32_t b[8][2];
#pragma unroll
            for (int nf = 0; nf < 8; nf++) {
                int col = warp_n + nf * 8 + gid;
                b[nf][0] = Bs[(kf * 8 + tig) * B_PAD + col];
                b[nf][1] = Bs[(kf * 8 + tig + 4) * B_PAD + col];
            }
#pragma unroll
            for (int mf = 0; mf < 2; mf++)
#pragma unroll
                for (int nf = 0; nf < 8; nf++)
                    mma_tf32(acc[mf][nf], a[mf], b[nf]);
        }
        __syncthreads();
    }

    // ---- writeback partials ----
    const int grow0 = g_off[o] + m0;
#pragma unroll
    for (int mf = 0; mf < 2; mf++) {
        int r0 = warp_m + mf * 16 + gid;
#pragma unroll
        for (int h = 0; h < 2; h++) {
            int r = r0 + h * 8;
            if (m0 + r < cnt) {
                float* dst = &g_hpart[c][grow0 + r][n0 + warp_n];
#pragma unroll
                for (int nf = 0; nf < 8; nf++)
                    *(float2*)(dst + nf * 8 + tig * 2) =
                        make_float2(acc[mf][nf][h * 2], acc[mf][nf][h * 2 + 1]);
            }
        }
    }
}

// ---------------------------------------------------------------
// Layer-1 epilogue: fixed-order split reduction + bias + leaky
// ---------------------------------------------------------------
__global__ void l1_epilogue(const float* __restrict__ b_in)
{
    const int r  = blockIdx.x;
    const int o  = g_rowo[r];
    const int ns = c_nsplit[o];
    const int j  = threadIdx.x * 4;
    float4 v = *(const float4*)(b_in + (size_t)o * H4 + j);
    for (int cc = 0; cc < ns; cc++) {
        float4 p = *(const float4*)(&g_hpart[cc][r][j]);
        v.x += p.x; v.y += p.y; v.z += p.z; v.w += p.w;
    }
    v.x = (v.x > 0.f) ? v.x : 0.2f * v.x;
    v.y = (v.y > 0.f) ? v.y : 0.2f * v.y;
    v.z = (v.z > 0.f) ? v.z : 0.2f * v.z;
    v.w = (v.w > 0.f) ? v.w : 0.2f * v.w;
    *(float4*)(g_h + (size_t)r * H4 + j) = v;
}

// ---------------------------------------------------------------
// Dense tf32 GEMM + bias + leaky, 64x64 tiles, 128 thr (4 warps 2x2),
// cp.async double-buffered. sel=0: g_h@W1->g_z1 ; sel=1: g_z1@W2->g_z2
// ---------------------------------------------------------------
__global__ __launch_bounds__(128)
void dense_mma(const float* __restrict__ B, const float* __restrict__ bias,
               int K, int N, int sel)
{
    const float* A = (sel == 0) ? g_h  : g_z1;
    float*       C = (sel == 0) ? g_z1 : g_z2;
    const int m0 = blockIdx.y * DM;
    const int n0 = blockIdx.x * DN;

    __shared__ uint32_t sA[2 * DA_TILE];
    __shared__ uint32_t sB[2 * DB_TILE];
    const uint32_t aOffB = (uint32_t)__cvta_generic_to_shared(sA);
    const uint32_t bOffB = (uint32_t)__cvta_generic_to_shared(sB);

    const int tid  = threadIdx.x;
    const int wid  = tid >> 5;
    const int lane = tid & 31;
    const int gid  = lane >> 2;
    const int tig  = lane & 3;
    const int warp_m = (wid >> 1) * 32;
    const int warp_n = (wid & 1) * 32;

    float acc[2][4][4];
#pragma unroll
    for (int i = 0; i < 2; i++)
#pragma unroll
        for (int j = 0; j < 4; j++)
#pragma unroll
            for (int q = 0; q < 4; q++) acc[i][j][q] = 0.f;

    auto issue = [&](int t) {
        const int k0  = t * BK;
        const int buf = t & 1;
#pragma unroll
        for (int j = 0; j < 4; j++) {
            int cch = tid + j * 128;
            int row = cch >> 3;
            int kc  = (cch & 7) * 4;
            uint32_t dst = aOffB + (uint32_t)(buf * DA_TILE + row * A_PAD + kc) * 4;
            cp16(dst, A + (size_t)(m0 + row) * K + k0 + kc, true);
        }
#pragma unroll
        for (int j = 0; j < 4; j++) {
            int cch = tid + j * 128;
            int kk  = cch >> 4;
            int col = (cch & 15) * 4;
            uint32_t dst = bOffB + (uint32_t)(buf * DB_TILE + kk * DB_PAD + col) * 4;
            cp16(dst, B + (size_t)(k0 + kk) * N + n0 + col, true);
        }
        CP_COMMIT();
    };

    const int T = K / BK;
    issue(0);
    for (int t = 0; t < T; t++) {
        if (t + 1 < T) { issue(t + 1); CP_WAIT1(); }
        else           { CP_WAIT0(); }
        __syncthreads();

        const uint32_t* As = sA + (t & 1) * DA_TILE;
        const uint32_t* Bs = sB + (t & 1) * DB_TILE;
#pragma unroll
        for (int kf = 0; kf < 4; kf++) {
            uint32_t a[2][4];
#pragma unroll
            for (int mf = 0; mf < 2; mf++) {
                int r = warp_m + mf * 16 + gid;
                a[mf][0] = As[r * A_PAD + kf * 8 + tig];
                a[mf][1] = As[(r + 8) * A_PAD + kf * 8 + tig];
                a[mf][2] = As[r * A_PAD + kf * 8 + tig + 4];
                a[mf][3] = As[(r + 8) * A_PAD + kf * 8 + tig + 4];
            }
            uint32_t b[4][2];
#pragma unroll
            for (int nf = 0; nf < 4; nf++) {
                int col = warp_n + nf * 8 + gid;
                b[nf][0] = Bs[(kf * 8 + tig) * DB_PAD + col];
                b[nf][1] = Bs[(kf * 8 + tig + 4) * DB_PAD + col];
            }
#pragma unroll
            for (int mf = 0; mf < 2; mf++)
#pragma unroll
                for (int nf = 0; nf < 4; nf++)
                    mma_tf32(acc[mf][nf], a[mf], b[nf]);
        }
        __syncthreads();
    }

#pragma unroll
    for (int mf = 0; mf < 2; mf++) {
        int r0 = warp_m + mf * 16 + gid;
#pragma unroll
        for (int h = 0; h < 2; h++) {
            int m = m0 + r0 + h * 8;
            float* dst = C + (size_t)m * N + n0 + warp_n;
            const float* bs = bias + n0 + warp_n;
#pragma unroll
            for (int nf = 0; nf < 4; nf++) {
                float x = acc[mf][nf][h * 2]     + __ldg(bs + nf * 8 + tig * 2);
                float y = acc[mf][nf][h * 2 + 1] + __ldg(bs + nf * 8 + tig * 2 + 1);
                x = (x > 0.f) ? x : 0.2f * x;
                y = (y > 0.f) ? y : 0.2f * y;
                *(float2*)(dst + nf * 8 + tig * 2) = make_float2(x, y);
            }
        }
    }
}

// ---------------------------------------------------------------
// Final 256->1 GEMV + sigmoid, scatter to original batch order.
// ---------------------------------------------------------------
__global__ void l4_kernel(const float* __restrict__ W3,
                          const float* __restrict__ b3,
                          float* __restrict__ out)
{
    const int warp = threadIdx.x >> 5;
    const int lane = threadIdx.x & 31;
    const int r = blockIdx.x * 8 + warp;
    const float* zv = g_z2 + (size_t)r * H1;
    float p = 0.f;
#pragma unroll
    for (int l = 0; l < 8; l++) p += zv[lane + l * 32] * W3[lane + l * 32];
#pragma unroll
    for (int d = 16; d; d >>= 1) p += __shfl_xor_sync(0xffffffffu, p, d);
    if (lane == 0) {
        float x = p + b3[0];
        out[g_rowb[r]] = 1.f / (1.f + expf(-x));
    }
}

// ---------------------------------------------------------------
extern "C" void kernel_launch(void* const* d_in, const int* in_sizes, int n_in,
                              void* d_out, int out_size)
{
    const float* mazes  = (const float*)d_in[0];
    const int*   orders = (const int*)  d_in[1];
    const float* embed  = (const float*)d_in[2];
    const float* W_in   = (const float*)d_in[3];
    const float* b_in   = (const float*)d_in[4];
    const float* W1     = (const float*)d_in[5];
    const float* b1     = (const float*)d_in[6];
    const float* W2     = (const float*)d_in[7];
    const float* b2     = (const float*)d_in[8];
    const float* W3     = (const float*)d_in[9];
    const float* b3     = (const float*)d_in[10];
    float* out = (float*)d_out;

    cudaFuncSetAttribute(layer1_mma, cudaFuncAttributeMaxDynamicSharedMemorySize, L1_SMEM);

    bucket_kernel<<<1, BATCH>>>(orders);
    layer1_mma<<<dim3(H4 / BN, BATCH / BM, NZ), 256, L1_SMEM>>>(mazes, W_in, embed);
    l1_epilogue<<<BATCH, 256>>>(b_in);
    dense_mma<<<dim3(H2 / DN, BATCH / DM), 128>>>(W1, b1, H4, H2, 0);
    dense_mma<<<dim3(H1 / DN, BATCH / DM), 128>>>(W2, b2, H2, H1, 1);
    l4_kernel<<<BATCH / 8, 256>>>(W3, b3, out);
}

// round 8
// speedup vs baseline: 2.3742x; 1.4089x over previous
#include <cuda_runtime.h>
#include <math.h>
#include <stdint.h>
#include <stddef.h>

// ---------------- problem constants ----------------
#define BATCH   1024
#define EMBED   16
#define S_MAX   16641
#define D_IN    16657
#define H4      1024
#define H2      512
#define H1      256
#define NEXP    7
#define KCHUNK  2048
#define NSPLIT_MAX 9
#define NZ      17
#define XSTRIDE 16672            // ceil(16657,32); 16B-aligned row pitch
#define XROWS   (BATCH + 128)    // padding rows stay zero

__constant__ int c_sizes[NEXP]  = {9, 25, 81, 289, 1089, 4225, 16641};
__constant__ int c_nsplit[NEXP] = {1, 1, 1, 1, 1, 3, 9};
__constant__ int c_zo[NZ] = {0,1,2,3,4,5,5,5,6,6,6,6,6,6,6,6,6};
__constant__ int c_zc[NZ] = {0,0,0,0,0,0,1,2,0,1,2,3,4,5,6,7,8};

// ---------------- device scratch (static) ----------------
__device__ int   g_cnt[NEXP];
__device__ int   g_off[NEXP + 1];
__device__ int   g_idx[NEXP * BATCH];
__device__ int   g_rowb[BATCH];
__device__ int   g_rowo[BATCH];
__device__ float g_xc[XROWS][XSTRIDE];             // packed X (maze+embed), compact order
__device__ float g_hpart[NSPLIT_MAX][BATCH][H4];
__device__ float g_h [BATCH * H4];
__device__ float g_z1[BATCH * H2];
__device__ float g_z2[BATCH * H1];

// ---------------- helpers ----------------
__device__ __forceinline__ void mma_tf32(float* c, const uint32_t* a, const uint32_t* b) {
    asm volatile(
        "mma.sync.aligned.m16n8k8.row.col.f32.tf32.tf32.f32 "
        "{%0,%1,%2,%3}, {%4,%5,%6,%7}, {%8,%9}, {%0,%1,%2,%3};"
        : "+f"(c[0]), "+f"(c[1]), "+f"(c[2]), "+f"(c[3])
        : "r"(a[0]), "r"(a[1]), "r"(a[2]), "r"(a[3]), "r"(b[0]), "r"(b[1]));
}
__device__ __forceinline__ void cp16(uint32_t dst, const void* src, bool p) {
    asm volatile("cp.async.cg.shared.global [%0], [%1], 16, %2;"
                 :: "r"(dst), "l"(src), "r"(p ? 16 : 0) : "memory");
}
#define CP_COMMIT() asm volatile("cp.async.commit_group;" ::: "memory")
#define CP_WAIT0()  asm volatile("cp.async.wait_group 0;" ::: "memory")
#define CP_WAIT1()  asm volatile("cp.async.wait_group 1;" ::: "memory")
#define CP_WAIT2()  asm volatile("cp.async.wait_group 2;" ::: "memory")
#define CP_WAIT3()  asm volatile("cp.async.wait_group 3;" ::: "memory")

// ---------------- tile geometry ----------------
#define BM 128
#define BN 128
#define BK 32
#define A_PAD 36
#define B_PAD 132
#define A_TILE (BM * A_PAD)                 // 4608 u32
#define B_TILE (BK * B_PAD)                 // 4224 u32
#define NST1 3
#define L1_SMEM (NST1 * (A_TILE + B_TILE) * 4)   // 105984 B

#define DM 64
#define DN 64
#define DB_PAD 68
#define DA_TILE (DM * A_PAD)                // 2304 u32
#define DB_TILE (BK * DB_PAD)               // 2176 u32
#define NSTD 4
#define D_SMEM (NSTD * (DA_TILE + DB_TILE) * 4)  // 71680 B

// ---------------------------------------------------------------
// bucket rows by expert
// ---------------------------------------------------------------
__global__ void bucket_kernel(const int* __restrict__ orders)
{
    __shared__ int s_cnt[NEXP];
    __shared__ int s_off[NEXP];
    int b = threadIdx.x;
    if (b < NEXP) s_cnt[b] = 0;
    __syncthreads();
    int o = orders[b];
    int pos = atomicAdd(&s_cnt[o], 1);
    __syncthreads();
    if (b == 0) {
        int a = 0;
        for (int i = 0; i < NEXP; i++) { s_off[i] = a; g_cnt[i] = s_cnt[i]; g_off[i] = a; a += s_cnt[i]; }
        g_off[NEXP] = a;
    }
    __syncthreads();
    g_idx[o * BATCH + pos] = b;
    int row = s_off[o] + pos;
    g_rowb[row] = b;
    g_rowo[row] = o;
}

// ---------------------------------------------------------------
// pack X: compact-row gather of maze slice + embed, zero pad to k-tile
// ---------------------------------------------------------------
__global__ void pack_kernel(const float* __restrict__ mazes,
                            const float* __restrict__ embed)
{
    const int r = blockIdx.x;
    const int b = g_rowb[r];
    const int o = g_rowo[r];
    const int s = c_sizes[o];
    const int Ktot = s + EMBED;
    const int kal  = (Ktot + 31) & ~31;
    const float* src = mazes + (size_t)b * S_MAX;
    float* dst = g_xc[r];
    for (int k = threadIdx.x; k < s; k += 256) dst[k] = src[k];
    for (int k = s + threadIdx.x; k < kal; k += 256)
        dst[k] = (k < Ktot) ? embed[o * EMBED + (k - s)] : 0.f;
}

// ---------------------------------------------------------------
// Layer-1 grouped tf32 GEMM, split-K, 3-stage cp.async pipeline.
// grid = (8 n-tiles, 8 m-tiles, 17 z), 256 threads (8 warps 4x2).
// ---------------------------------------------------------------
__global__ __launch_bounds__(256)
void layer1_mma(const float* __restrict__ W_in)
{
    const int z = blockIdx.z;
    const int o = c_zo[z];
    const int c = c_zc[z];
    const int cnt = g_cnt[o];
    const int m0 = blockIdx.y * BM;
    if (m0 >= cnt) return;
    const int s    = c_sizes[o];
    const int Ktot = s + EMBED;
    const int kbeg = c * KCHUNK;
    if (kbeg >= Ktot) return;
    const int kend = min(kbeg + KCHUNK, Ktot);
    const int n0   = blockIdx.x * BN;

    extern __shared__ uint32_t sm[];
    uint32_t* AsBuf = sm;
    uint32_t* BsBuf = sm + NST1 * A_TILE;
    const uint32_t smb  = (uint32_t)__cvta_generic_to_shared(sm);
    const uint32_t aOffB = smb;
    const uint32_t bOffB = smb + NST1 * A_TILE * 4;

    const int tid  = threadIdx.x;
    const int wid  = tid >> 5;
    const int lane = tid & 31;
    const int gid  = lane >> 2;
    const int tig  = lane & 3;
    const int warp_m = (wid >> 1) * 32;
    const int warp_n = (wid & 1) * 64;

    const int arow0 = g_off[o] + m0;       // compact row base (contiguous!)
    const float* wexp = W_in + (size_t)o * D_IN * H4;

    float acc[2][8][4];
#pragma unroll
    for (int i = 0; i < 2; i++)
#pragma unroll
        for (int j = 0; j < 8; j++)
#pragma unroll
            for (int q = 0; q < 4; q++) acc[i][j][q] = 0.f;

    const int T = (kend - kbeg + BK - 1) / BK;

    auto issue = [&](int t) {
        const int k0  = kbeg + t * BK;
        const int buf = t % NST1;
        // A: 128 rows x 32 k, 4 cp16/thread, unconditional (packed & padded)
#pragma unroll
        for (int j = 0; j < 4; j++) {
            int cch = tid + j * 256;
            int row = cch >> 3;
            int kc  = (cch & 7) * 4;
            uint32_t dst = aOffB + (uint32_t)(buf * A_TILE + row * A_PAD + kc) * 4;
            cp16(dst, &g_xc[arow0 + row][k0 + kc], true);
        }
        // B: 32 k x 128 n
#pragma unroll
        for (int j = 0; j < 4; j++) {
            int cch = tid + j * 256;
            int kk  = cch >> 5;
            int col = (cch & 31) * 4;
            int k   = k0 + kk;
            bool p  = (k < kend);
            int wr  = p ? ((k < s) ? k : (S_MAX + (k - s))) : 0;
            uint32_t dst = bOffB + (uint32_t)(buf * B_TILE + kk * B_PAD + col) * 4;
            cp16(dst, wexp + (size_t)wr * H4 + n0 + col, p);
        }
        CP_COMMIT();
    };

    issue(0);
    if (T > 1) issue(1);
    for (int t = 0; t < T; t++) {
        if (t + 2 < T) { issue(t + 2); CP_WAIT2(); }
        else if (t + 1 < T) { CP_WAIT1(); }
        else { CP_WAIT0(); }
        __syncthreads();

        const uint32_t* As = AsBuf + (t % NST1) * A_TILE;
        const uint32_t* Bs = BsBuf + (t % NST1) * B_TILE;
#pragma unroll
        for (int kf = 0; kf < 4; kf++) {
            uint32_t a[2][4];
#pragma unroll
            for (int mf = 0; mf < 2; mf++) {
                int r = warp_m + mf * 16 + gid;
                a[mf][0] = As[r * A_PAD + kf * 8 + tig];
                a[mf][1] = As[(r + 8) * A_PAD + kf * 8 + tig];
                a[mf][2] = As[r * A_PAD + kf * 8 + tig + 4];
                a[mf][3] = As[(r + 8) * A_PAD + kf * 8 + tig + 4];
            }
            uint32_t b[8][2];
#pragma unroll
            for (int nf = 0; nf < 8; nf++) {
                int col = warp_n + nf * 8 + gid;
                b[nf][0] = Bs[(kf * 8 + tig) * B_PAD + col];
                b[nf][1] = Bs[(kf * 8 + tig + 4) * B_PAD + col];
            }
#pragma unroll
            for (int mf = 0; mf < 2; mf++)
#pragma unroll
                for (int nf = 0; nf < 8; nf++)
                    mma_tf32(acc[mf][nf], a[mf], b[nf]);
        }
        __syncthreads();
    }

    // ---- writeback partials ----
    const int grow0 = g_off[o] + m0;
#pragma unroll
    for (int mf = 0; mf < 2; mf++) {
        int r0 = warp_m + mf * 16 + gid;
#pragma unroll
        for (int h = 0; h < 2; h++) {
            int r = r0 + h * 8;
            if (m0 + r < cnt) {
                float* dst = &g_hpart[c][grow0 + r][n0 + warp_n];
#pragma unroll
                for (int nf = 0; nf < 8; nf++)
                    *(float2*)(dst + nf * 8 + tig * 2) =
                        make_float2(acc[mf][nf][h * 2], acc[mf][nf][h * 2 + 1]);
            }
        }
    }
}

// ---------------------------------------------------------------
// Layer-1 epilogue: fixed-order split reduction + bias + leaky
// ---------------------------------------------------------------
__global__ void l1_epilogue(const float* __restrict__ b_in)
{
    const int r  = blockIdx.x;
    const int o  = g_rowo[r];
    const int ns = c_nsplit[o];
    const int j  = threadIdx.x * 4;
    float4 v = *(const float4*)(b_in + (size_t)o * H4 + j);
    for (int cc = 0; cc < ns; cc++) {
        float4 p = *(const float4*)(&g_hpart[cc][r][j]);
        v.x += p.x; v.y += p.y; v.z += p.z; v.w += p.w;
    }
    v.x = (v.x > 0.f) ? v.x : 0.2f * v.x;
    v.y = (v.y > 0.f) ? v.y : 0.2f * v.y;
    v.z = (v.z > 0.f) ? v.z : 0.2f * v.z;
    v.w = (v.w > 0.f) ? v.w : 0.2f * v.w;
    *(float4*)(g_h + (size_t)r * H4 + j) = v;
}

// ---------------------------------------------------------------
// Dense tf32 GEMM + bias + leaky, 64x64 tiles, 128 thr, 4-stage pipe.
// sel=0: g_h@W1->g_z1 ; sel=1: g_z1@W2->g_z2
// ---------------------------------------------------------------
__global__ __launch_bounds__(128)
void dense_mma(const float* __restrict__ B, const float* __restrict__ bias,
               int K, int N, int sel)
{
    const float* A = (sel == 0) ? g_h  : g_z1;
    float*       C = (sel == 0) ? g_z1 : g_z2;
    const int m0 = blockIdx.y * DM;
    const int n0 = blockIdx.x * DN;

    extern __shared__ uint32_t sm[];
    uint32_t* sA = sm;
    uint32_t* sB = sm + NSTD * DA_TILE;
    const uint32_t aOffB = (uint32_t)__cvta_generic_to_shared(sA);
    const uint32_t bOffB = (uint32_t)__cvta_generic_to_shared(sB);

    const int tid  = threadIdx.x;
    const int wid  = tid >> 5;
    const int lane = tid & 31;
    const int gid  = lane >> 2;
    const int tig  = lane & 3;
    const int warp_m = (wid >> 1) * 32;
    const int warp_n = (wid & 1) * 32;

    float acc[2][4][4];
#pragma unroll
    for (int i = 0; i < 2; i++)
#pragma unroll
        for (int j = 0; j < 4; j++)
#pragma unroll
            for (int q = 0; q < 4; q++) acc[i][j][q] = 0.f;

    auto issue = [&](int t) {
        const int k0  = t * BK;
        const int buf = t % NSTD;
#pragma unroll
        for (int j = 0; j < 4; j++) {
            int cch = tid + j * 128;
            int row = cch >> 3;
            int kc  = (cch & 7) * 4;
            uint32_t dst = aOffB + (uint32_t)(buf * DA_TILE + row * A_PAD + kc) * 4;
            cp16(dst, A + (size_t)(m0 + row) * K + k0 + kc, true);
        }
#pragma unroll
        for (int j = 0; j < 4; j++) {
            int cch = tid + j * 128;
            int kk  = cch >> 4;
            int col = (cch & 15) * 4;
            uint32_t dst = bOffB + (uint32_t)(buf * DB_TILE + kk * DB_PAD + col) * 4;
            cp16(dst, B + (size_t)(k0 + kk) * N + n0 + col, true);
        }
        CP_COMMIT();
    };

    const int T = K / BK;
    issue(0);
    if (T > 1) issue(1);
    if (T > 2) issue(2);
    for (int t = 0; t < T; t++) {
        if (t + 3 < T) { issue(t + 3); CP_WAIT3(); }
        else if (t + 2 < T) { CP_WAIT2(); }
        else if (t + 1 < T) { CP_WAIT1(); }
        else { CP_WAIT0(); }
        __syncthreads();

        const uint32_t* As = sA + (t % NSTD) * DA_TILE;
        const uint32_t* Bs = sB + (t % NSTD) * DB_TILE;
#pragma unroll
        for (int kf = 0; kf < 4; kf++) {
            uint32_t a[2][4];
#pragma unroll
            for (int mf = 0; mf < 2; mf++) {
                int r = warp_m + mf * 16 + gid;
                a[mf][0] = As[r * A_PAD + kf * 8 + tig];
                a[mf][1] = As[(r + 8) * A_PAD + kf * 8 + tig];
                a[mf][2] = As[r * A_PAD + kf * 8 + tig + 4];
                a[mf][3] = As[(r + 8) * A_PAD + kf * 8 + tig + 4];
            }
            uint32_t b[4][2];
#pragma unroll
            for (int nf = 0; nf < 4; nf++) {
                int col = warp_n + nf * 8 + gid;
                b[nf][0] = Bs[(kf * 8 + tig) * DB_PAD + col];
                b[nf][1] = Bs[(kf * 8 + tig + 4) * DB_PAD + col];
            }
#pragma unroll
            for (int mf = 0; mf < 2; mf++)
#pragma unroll
                for (int nf = 0; nf < 4; nf++)
                    mma_tf32(acc[mf][nf], a[mf], b[nf]);
        }
        __syncthreads();
    }

#pragma unroll
    for (int mf = 0; mf < 2; mf++) {
        int r0 = warp_m + mf * 16 + gid;
#pragma unroll
        for (int h = 0; h < 2; h++) {
            int m = m0 + r0 + h * 8;
            float* dst = C + (size_t)m * N + n0 + warp_n;
            const float* bs = bias + n0 + warp_n;
#pragma unroll
            for (int nf = 0; nf < 4; nf++) {
                float x = acc[mf][nf][h * 2]     + __ldg(bs + nf * 8 + tig * 2);
                float y = acc[mf][nf][h * 2 + 1] + __ldg(bs + nf * 8 + tig * 2 + 1);
                x = (x > 0.f) ? x : 0.2f * x;
                y = (y > 0.f) ? y : 0.2f * y;
                *(float2*)(dst + nf * 8 + tig * 2) = make_float2(x, y);
            }
        }
    }
}

// ---------------------------------------------------------------
// Final 256->1 GEMV + sigmoid, scatter to original batch order.
// ---------------------------------------------------------------
__global__ void l4_kernel(const float* __restrict__ W3,
                          const float* __restrict__ b3,
                          float* __restrict__ out)
{
    const int warp = threadIdx.x >> 5;
    const int lane = threadIdx.x & 31;
    const int r = blockIdx.x * 8 + warp;
    const float* zv = g_z2 + (size_t)r * H1;
    float p = 0.f;
#pragma unroll
    for (int l = 0; l < 8; l++) p += zv[lane + l * 32] * W3[lane + l * 32];
#pragma unroll
    for (int d = 16; d; d >>= 1) p += __shfl_xor_sync(0xffffffffu, p, d);
    if (lane == 0) {
        float x = p + b3[0];
        out[g_rowb[r]] = 1.f / (1.f + expf(-x));
    }
}

// ---------------------------------------------------------------
extern "C" void kernel_launch(void* const* d_in, const int* in_sizes, int n_in,
                              void* d_out, int out_size)
{
    const float* mazes  = (const float*)d_in[0];
    const int*   orders = (const int*)  d_in[1];
    const float* embed  = (const float*)d_in[2];
    const float* W_in   = (const float*)d_in[3];
    const float* b_in   = (const float*)d_in[4];
    const float* W1     = (const float*)d_in[5];
    const float* b1     = (const float*)d_in[6];
    const float* W2     = (const float*)d_in[7];
    const float* b2     = (const float*)d_in[8];
    const float* W3     = (const float*)d_in[9];
    const float* b3     = (const float*)d_in[10];
    float* out = (float*)d_out;

    cudaFuncSetAttribute(layer1_mma, cudaFuncAttributeMaxDynamicSharedMemorySize, L1_SMEM);
    cudaFuncSetAttribute(dense_mma,  cudaFuncAttributeMaxDynamicSharedMemorySize, D_SMEM);

    bucket_kernel<<<1, BATCH>>>(orders);
    pack_kernel<<<BATCH, 256>>>(mazes, embed);
    layer1_mma<<<dim3(H4 / BN, BATCH / BM, NZ), 256, L1_SMEM>>>(W_in);
    l1_epilogue<<<BATCH, 256>>>(b_in);
    dense_mma<<<dim3(H2 / DN, BATCH / DM), 128, D_SMEM>>>(W1, b1, H4, H2, 0);
    dense_mma<<<dim3(H1 / DN, BATCH / DM), 128, D_SMEM>>>(W2, b2, H2, H1, 1);
    l4_kernel<<<BATCH / 8, 256>>>(W3, b3, out);
}

// round 9
// speedup vs baseline: 3.5351x; 1.4890x over previous
#include <cuda_runtime.h>
#include <math.h>
#include <stdint.h>
#include <stddef.h>

// ---------------- problem constants ----------------
#define BATCH   1024
#define EMBED   16
#define S_MAX   16641
#define D_IN    16657
#define H4      1024
#define H2      512
#define H1      256
#define NEXP    7
#define KCHUNK  2048
#define NSPLIT_MAX 9
#define NZ      17
#define XSTRIDE 16672
#define XROWS   (BATCH + 128)

__constant__ int c_sizes[NEXP]  = {9, 25, 81, 289, 1089, 4225, 16641};
__constant__ int c_nsplit[NEXP] = {1, 1, 1, 1, 1, 3, 9};
// heavy-first z order: expert 6 splits, then 5, then the small ones
__constant__ int c_zo[NZ] = {6,6,6,6,6,6,6,6,6, 5,5,5, 4,3,2,1,0};
__constant__ int c_zc[NZ] = {0,1,2,3,4,5,6,7,8, 0,1,2, 0,0,0,0,0};

// ---------------- device scratch (static) ----------------
__device__ int   g_cnt[NEXP];
__device__ int   g_off[NEXP + 1];
__device__ int   g_idx[NEXP * BATCH];
__device__ int   g_rowb[BATCH];
__device__ int   g_rowo[BATCH];
__device__ float g_xc[XROWS][XSTRIDE];
__device__ float g_hpart[NSPLIT_MAX][BATCH][H4];
__device__ float g_h [BATCH * H4];
__device__ float g_z1[BATCH * H2];
__device__ float g_z2[BATCH * H1];

// ---------------- helpers ----------------
__device__ __forceinline__ void mma_tf32(float* c, const uint32_t* a, const uint32_t* b) {
    asm volatile(
        "mma.sync.aligned.m16n8k8.row.col.f32.tf32.tf32.f32 "
        "{%0,%1,%2,%3}, {%4,%5,%6,%7}, {%8,%9}, {%0,%1,%2,%3};"
        : "+f"(c[0]), "+f"(c[1]), "+f"(c[2]), "+f"(c[3])
        : "r"(a[0]), "r"(a[1]), "r"(a[2]), "r"(a[3]), "r"(b[0]), "r"(b[1]));
}
__device__ __forceinline__ void cp16(uint32_t dst, const void* src, bool p) {
    asm volatile("cp.async.cg.shared.global [%0], [%1], 16, %2;"
                 :: "r"(dst), "l"(src), "r"(p ? 16 : 0) : "memory");
}
#define CP_COMMIT() asm volatile("cp.async.commit_group;" ::: "memory")
#define CP_WAIT0()  asm volatile("cp.async.wait_group 0;" ::: "memory")
#define CP_WAIT1()  asm volatile("cp.async.wait_group 1;" ::: "memory")
#define CP_WAIT2()  asm volatile("cp.async.wait_group 2;" ::: "memory")

// ---------------- tile geometry ----------------
#define BK 32
// layer 1: 64 x 128 tile, 256 threads (8 warps, 2x4, warp tile 32x32)
#define BM 64
#define BN 128
#define A_PAD 36
#define B_PAD 132
#define A_TILE (BM * A_PAD)                 // 2304 u32
#define B_TILE (BK * B_PAD)                 // 4224 u32
#define NST1 3
#define L1_SMEM (NST1 * (A_TILE + B_TILE) * 4)   // 78336 B -> 2 CTAs/SM

// dense: 32 x 64 tile, 128 threads (4 warps, warp tile 32x16)
#define DM 32
#define DN 64
#define DB_PAD 68
#define DA_TILE (DM * A_PAD)                // 1152 u32
#define DB_TILE (BK * DB_PAD)               // 2176 u32
#define NSTD 3
#define D_SMEM (NSTD * (DA_TILE + DB_TILE) * 4)  // 39936 B

// ---------------------------------------------------------------
__global__ void bucket_kernel(const int* __restrict__ orders)
{
    __shared__ int s_cnt[NEXP];
    __shared__ int s_off[NEXP];
    int b = threadIdx.x;
    if (b < NEXP) s_cnt[b] = 0;
    __syncthreads();
    int o = orders[b];
    int pos = atomicAdd(&s_cnt[o], 1);
    __syncthreads();
    if (b == 0) {
        int a = 0;
        for (int i = 0; i < NEXP; i++) { s_off[i] = a; g_cnt[i] = s_cnt[i]; g_off[i] = a; a += s_cnt[i]; }
        g_off[NEXP] = a;
    }
    __syncthreads();
    g_idx[o * BATCH + pos] = b;
    int row = s_off[o] + pos;
    g_rowb[row] = b;
    g_rowo[row] = o;
}

// ---------------------------------------------------------------
// pack X: compact-row gather of maze slice + embed, zero pad to k-tile
// ---------------------------------------------------------------
__global__ void pack_kernel(const float* __restrict__ mazes,
                            const float* __restrict__ embed)
{
    const int r = blockIdx.x;
    const int b = g_rowb[r];
    const int o = g_rowo[r];
    const int s = c_sizes[o];
    const int Ktot = s + EMBED;
    const int kal  = (Ktot + 31) & ~31;
    const float* src = mazes + (size_t)b * S_MAX;
    float* dst = g_xc[r];
    for (int k = threadIdx.x; k < s; k += 256) dst[k] = src[k];
    for (int k = s + threadIdx.x; k < kal; k += 256)
        dst[k] = (k < Ktot) ? embed[o * EMBED + (k - s)] : 0.f;
}

// ---------------------------------------------------------------
// Layer-1 grouped tf32 GEMM, split-K, 3-stage pipeline, 64x128 tile.
// grid = (8 n-tiles, 16 m-tiles, 17 z), 256 threads.
// Single-split experts get bias+leaky fused here (write g_h directly).
// ---------------------------------------------------------------
__global__ __launch_bounds__(256)
void layer1_mma(const float* __restrict__ W_in,
                const float* __restrict__ b_in)
{
    const int z = blockIdx.z;
    const int o = c_zo[z];
    const int c = c_zc[z];
    const int cnt = g_cnt[o];
    const int m0 = blockIdx.y * BM;
    if (m0 >= cnt) return;
    const int s    = c_sizes[o];
    const int Ktot = s + EMBED;
    const int kbeg = c * KCHUNK;
    if (kbeg >= Ktot) return;
    const int kend = min(kbeg + KCHUNK, Ktot);
    const int n0   = blockIdx.x * BN;
    const int ns   = c_nsplit[o];

    extern __shared__ uint32_t sm[];
    uint32_t* AsBuf = sm;
    uint32_t* BsBuf = sm + NST1 * A_TILE;
    const uint32_t smb  = (uint32_t)__cvta_generic_to_shared(sm);
    const uint32_t aOffB = smb;
    const uint32_t bOffB = smb + NST1 * A_TILE * 4;

    const int tid  = threadIdx.x;
    const int wid  = tid >> 5;
    const int lane = tid & 31;
    const int gid  = lane >> 2;
    const int tig  = lane & 3;
    const int warp_m = (wid >> 2) * 32;       // 2 row-groups
    const int warp_n = (wid & 3) * 32;        // 4 col-groups

    const int arow0 = g_off[o] + m0;
    const float* wexp = W_in + (size_t)o * D_IN * H4;

    float acc[2][4][4];
#pragma unroll
    for (int i = 0; i < 2; i++)
#pragma unroll
        for (int j = 0; j < 4; j++)
#pragma unroll
            for (int q = 0; q < 4; q++) acc[i][j][q] = 0.f;

    const int T = (kend - kbeg + BK - 1) / BK;

    auto issue = [&](int t) {
        const int k0  = kbeg + t * BK;
        const int buf = t % NST1;
        // A: 64 rows x 32 k -> 512 float4, 2 per thread
#pragma unroll
        for (int j = 0; j < 2; j++) {
            int cch = tid + j * 256;
            int row = cch >> 3;
            int kc  = (cch & 7) * 4;
            uint32_t dst = aOffB + (uint32_t)(buf * A_TILE + row * A_PAD + kc) * 4;
            cp16(dst, &g_xc[arow0 + row][k0 + kc], true);
        }
        // B: 32 k x 128 n -> 1024 float4, 4 per thread
#pragma unroll
        for (int j = 0; j < 4; j++) {
            int cch = tid + j * 256;
            int kk  = cch >> 5;
            int col = (cch & 31) * 4;
            int k   = k0 + kk;
            bool p  = (k < kend);
            int wr  = p ? ((k < s) ? k : (S_MAX + (k - s))) : 0;
            uint32_t dst = bOffB + (uint32_t)(buf * B_TILE + kk * B_PAD + col) * 4;
            cp16(dst, wexp + (size_t)wr * H4 + n0 + col, p);
        }
        CP_COMMIT();
    };

    issue(0);
    if (T > 1) issue(1);
    for (int t = 0; t < T; t++) {
        if (t + 2 < T) { issue(t + 2); CP_WAIT2(); }
        else if (t + 1 < T) { CP_WAIT1(); }
        else { CP_WAIT0(); }
        __syncthreads();

        const uint32_t* As = AsBuf + (t % NST1) * A_TILE;
        const uint32_t* Bs = BsBuf + (t % NST1) * B_TILE;
#pragma unroll
        for (int kf = 0; kf < 4; kf++) {
            uint32_t a[2][4];
#pragma unroll
            for (int mf = 0; mf < 2; mf++) {
                int r = warp_m + mf * 16 + gid;
                a[mf][0] = As[r * A_PAD + kf * 8 + tig];
                a[mf][1] = As[(r + 8) * A_PAD + kf * 8 + tig];
                a[mf][2] = As[r * A_PAD + kf * 8 + tig + 4];
                a[mf][3] = As[(r + 8) * A_PAD + kf * 8 + tig + 4];
            }
            uint32_t b[4][2];
#pragma unroll
            for (int nf = 0; nf < 4; nf++) {
                int col = warp_n + nf * 8 + gid;
                b[nf][0] = Bs[(kf * 8 + tig) * B_PAD + col];
                b[nf][1] = Bs[(kf * 8 + tig + 4) * B_PAD + col];
            }
#pragma unroll
            for (int mf = 0; mf < 2; mf++)
#pragma unroll
                for (int nf = 0; nf < 4; nf++)
                    mma_tf32(acc[mf][nf], a[mf], b[nf]);
        }
        __syncthreads();
    }

    // ---- writeback ----
    const int grow0 = g_off[o] + m0;
#pragma unroll
    for (int mf = 0; mf < 2; mf++) {
#pragma unroll
        for (int h = 0; h < 2; h++) {
            int r = warp_m + mf * 16 + gid + h * 8;
            if (m0 + r < cnt) {
                if (ns == 1) {
                    float* dst = g_h + (size_t)(grow0 + r) * H4 + n0 + warp_n;
                    const float* bs = b_in + (size_t)o * H4 + n0 + warp_n;
#pragma unroll
                    for (int nf = 0; nf < 4; nf++) {
                        float x = acc[mf][nf][h * 2]     + __ldg(bs + nf * 8 + tig * 2);
                        float y = acc[mf][nf][h * 2 + 1] + __ldg(bs + nf * 8 + tig * 2 + 1);
                        x = (x > 0.f) ? x : 0.2f * x;
                        y = (y > 0.f) ? y : 0.2f * y;
                        *(float2*)(dst + nf * 8 + tig * 2) = make_float2(x, y);
                    }
                } else {
                    float* dst = &g_hpart[c][grow0 + r][n0 + warp_n];
#pragma unroll
                    for (int nf = 0; nf < 4; nf++)
                        *(float2*)(dst + nf * 8 + tig * 2) =
                            make_float2(acc[mf][nf][h * 2], acc[mf][nf][h * 2 + 1]);
                }
            }
        }
    }
}

// ---------------------------------------------------------------
// Layer-1 epilogue: only multi-split experts (5,6).
// ---------------------------------------------------------------
__global__ void l1_epilogue(const float* __restrict__ b_in)
{
    const int r  = blockIdx.x;
    const int o  = g_rowo[r];
    const int ns = c_nsplit[o];
    if (ns == 1) return;
    const int j  = threadIdx.x * 4;
    float4 v = *(const float4*)(b_in + (size_t)o * H4 + j);
    for (int cc = 0; cc < ns; cc++) {
        float4 p = *(const float4*)(&g_hpart[cc][r][j]);
        v.x += p.x; v.y += p.y; v.z += p.z; v.w += p.w;
    }
    v.x = (v.x > 0.f) ? v.x : 0.2f * v.x;
    v.y = (v.y > 0.f) ? v.y : 0.2f * v.y;
    v.z = (v.z > 0.f) ? v.z : 0.2f * v.z;
    v.w = (v.w > 0.f) ? v.w : 0.2f * v.w;
    *(float4*)(g_h + (size_t)r * H4 + j) = v;
}

// ---------------------------------------------------------------
// Dense tf32 GEMM + bias + leaky, 32x64 tiles, 128 thr, 3-stage.
// sel=0: g_h@W1->g_z1 ; sel=1: g_z1@W2->g_z2
// ---------------------------------------------------------------
__global__ __launch_bounds__(128)
void dense_mma(const float* __restrict__ B, const float* __restrict__ bias,
               int K, int N, int sel)
{
    const float* A = (sel == 0) ? g_h  : g_z1;
    float*       C = (sel == 0) ? g_z1 : g_z2;
    const int m0 = blockIdx.y * DM;
    const int n0 = blockIdx.x * DN;

    extern __shared__ uint32_t sm[];
    uint32_t* sA = sm;
    uint32_t* sB = sm + NSTD * DA_TILE;
    const uint32_t aOffB = (uint32_t)__cvta_generic_to_shared(sA);
    const uint32_t bOffB = (uint32_t)__cvta_generic_to_shared(sB);

    const int tid  = threadIdx.x;
    const int wid  = tid >> 5;
    const int lane = tid & 31;
    const int gid  = lane >> 2;
    const int tig  = lane & 3;
    const int warp_n = wid * 16;            // 4 warps cover 64 cols

    float acc[2][2][4];
#pragma unroll
    for (int i = 0; i < 2; i++)
#pragma unroll
        for (int j = 0; j < 2; j++)
#pragma unroll
            for (int q = 0; q < 4; q++) acc[i][j][q] = 0.f;

    auto issue = [&](int t) {
        const int k0  = t * BK;
        const int buf = t % NSTD;
        // A: 32 rows x 32 k -> 256 float4, 2 per thread
#pragma unroll
        for (int j = 0; j < 2; j++) {
            int cch = tid + j * 128;
            int row = cch >> 3;
            int kc  = (cch & 7) * 4;
            uint32_t dst = aOffB + (uint32_t)(buf * DA_TILE + row * A_PAD + kc) * 4;
            cp16(dst, A + (size_t)(m0 + row) * K + k0 + kc, true);
        }
        // B: 32 k x 64 n -> 512 float4, 4 per thread
#pragma unroll
        for (int j = 0; j < 4; j++) {
            int cch = tid + j * 128;
            int kk  = cch >> 4;
            int col = (cch & 15) * 4;
            uint32_t dst = bOffB + (uint32_t)(buf * DB_TILE + kk * DB_PAD + col) * 4;
            cp16(dst, B + (size_t)(k0 + kk) * N + n0 + col, true);
        }
        CP_COMMIT();
    };

    const int T = K / BK;
    issue(0);
    if (T > 1) issue(1);
    for (int t = 0; t < T; t++) {
        if (t + 2 < T) { issue(t + 2); CP_WAIT2(); }
        else if (t + 1 < T) { CP_WAIT1(); }
        else { CP_WAIT0(); }
        __syncthreads();

        const uint32_t* As = sA + (t % NSTD) * DA_TILE;
        const uint32_t* Bs = sB + (t % NSTD) * DB_TILE;
#pragma unroll
        for (int kf = 0; kf < 4; kf++) {
            uint32_t a[2][4];
#pragma unroll
            for (int mf = 0; mf < 2; mf++) {
                int r = mf * 16 + gid;
                a[mf][0] = As[r * A_PAD + kf * 8 + tig];
                a[mf][1] = As[(r + 8) * A_PAD + kf * 8 + tig];
                a[mf][2] = As[r * A_PAD + kf * 8 + tig + 4];
                a[mf][3] = As[(r + 8) * A_PAD + kf * 8 + tig + 4];
            }
            uint32_t b[2][2];
#pragma unroll
            for (int nf = 0; nf < 2; nf++) {
                int col = warp_n + nf * 8 + gid;
                b[nf][0] = Bs[(kf * 8 + tig) * DB_PAD + col];
                b[nf][1] = Bs[(kf * 8 + tig + 4) * DB_PAD + col];
            }
#pragma unroll
            for (int mf = 0; mf < 2; mf++)
#pragma unroll
                for (int nf = 0; nf < 2; nf++)
                    mma_tf32(acc[mf][nf], a[mf], b[nf]);
        }
        __syncthreads();
    }

#pragma unroll
    for (int mf = 0; mf < 2; mf++) {
#pragma unroll
        for (int h = 0; h < 2; h++) {
            int m = m0 + mf * 16 + gid + h * 8;
            float* dst = C + (size_t)m * N + n0 + warp_n;
            const float* bs = bias + n0 + warp_n;
#pragma unroll
            for (int nf = 0; nf < 2; nf++) {
                float x = acc[mf][nf][h * 2]     + __ldg(bs + nf * 8 + tig * 2);
                float y = acc[mf][nf][h * 2 + 1] + __ldg(bs + nf * 8 + tig * 2 + 1);
                x = (x > 0.f) ? x : 0.2f * x;
                y = (y > 0.f) ? y : 0.2f * y;
                *(float2*)(dst + nf * 8 + tig * 2) = make_float2(x, y);
            }
        }
    }
}

// ---------------------------------------------------------------
// Final 256->1 GEMV + sigmoid, scatter to original batch order.
// ---------------------------------------------------------------
__global__ void l4_kernel(const float* __restrict__ W3,
                          const float* __restrict__ b3,
                          float* __restrict__ out)
{
    const int warp = threadIdx.x >> 5;
    const int lane = threadIdx.x & 31;
    const int r = blockIdx.x * 8 + warp;
    const float* zv = g_z2 + (size_t)r * H1;
    float p = 0.f;
#pragma unroll
    for (int l = 0; l < 8; l++) p += zv[lane + l * 32] * W3[lane + l * 32];
#pragma unroll
    for (int d = 16; d; d >>= 1) p += __shfl_xor_sync(0xffffffffu, p, d);
    if (lane == 0) {
        float x = p + b3[0];
        out[g_rowb[r]] = 1.f / (1.f + expf(-x));
    }
}

// ---------------------------------------------------------------
extern "C" void kernel_launch(void* const* d_in, const int* in_sizes, int n_in,
                              void* d_out, int out_size)
{
    const float* mazes  = (const float*)d_in[0];
    const int*   orders = (const int*)  d_in[1];
    const float* embed  = (const float*)d_in[2];
    const float* W_in   = (const float*)d_in[3];
    const float* b_in   = (const float*)d_in[4];
    const float* W1     = (const float*)d_in[5];
    const float* b1     = (const float*)d_in[6];
    const float* W2     = (const float*)d_in[7];
    const float* b2     = (const float*)d_in[8];
    const float* W3     = (const float*)d_in[9];
    const float* b3     = (const float*)d_in[10];
    float* out = (float*)d_out;

    cudaFuncSetAttribute(layer1_mma, cudaFuncAttributeMaxDynamicSharedMemorySize, L1_SMEM);
    cudaFuncSetAttribute(dense_mma,  cudaFuncAttributeMaxDynamicSharedMemorySize, D_SMEM);

    bucket_kernel<<<1, BATCH>>>(orders);
    pack_kernel<<<BATCH, 256>>>(mazes, embed);
    layer1_mma<<<dim3(H4 / BN, BATCH / BM, NZ), 256, L1_SMEM>>>(W_in, b_in);
    l1_epilogue<<<BATCH, 256>>>(b_in);
    dense_mma<<<dim3(H2 / DN, BATCH / DM), 128, D_SMEM>>>(W1, b1, H4, H2, 0);
    dense_mma<<<dim3(H1 / DN, BATCH / DM), 128, D_SMEM>>>(W2, b2, H2, H1, 1);
    l4_kernel<<<BATCH / 8, 256>>>(W3, b3, out);
}

// round 11
// speedup vs baseline: 3.6957x; 1.0454x over previous
#include <cuda_runtime.h>
#include <cuda_fp16.h>
#include <math.h>
#include <stdint.h>
#include <stddef.h>

// ---------------- problem constants ----------------
#define BATCH   1024
#define EMBED   16
#define S_MAX   16641
#define D_IN    16657
#define H4      1024
#define H2      512
#define H1      256
#define NEXP    7
#define KCHUNK  2048
#define NSPLIT_MAX 9
#define NZ      17
#define XSTRIDE 16672
#define XROWS   (BATCH + 128)

__constant__ int c_sizes[NEXP]  = {9, 25, 81, 289, 1089, 4225, 16641};
__constant__ int c_nsplit[NEXP] = {1, 1, 1, 1, 1, 3, 9};
// heavy-first z order
__constant__ int c_zo[NZ] = {6,6,6,6,6,6,6,6,6, 5,5,5, 4,3,2,1,0};
__constant__ int c_zc[NZ] = {0,1,2,3,4,5,6,7,8, 0,1,2, 0,0,0,0,0};

// ---------------- device scratch (static) ----------------
__device__ int    g_cnt[NEXP];
__device__ int    g_off[NEXP + 1];
__device__ int    g_idx[NEXP * BATCH];
__device__ int    g_rowb[BATCH];
__device__ int    g_rowo[BATCH];
__device__ __half g_xch[XROWS][XSTRIDE];          // packed X as f16 (zero-init)
__device__ float  g_hpart[NSPLIT_MAX][BATCH][H4];
__device__ float  g_h [BATCH * H4];
__device__ float  g_z1[BATCH * H2];
__device__ float  g_z2[BATCH * H1];

// ---------------- helpers ----------------
__device__ __forceinline__ void mma_tf32(float* c, const uint32_t* a, const uint32_t* b) {
    asm volatile(
        "mma.sync.aligned.m16n8k8.row.col.f32.tf32.tf32.f32 "
        "{%0,%1,%2,%3}, {%4,%5,%6,%7}, {%8,%9}, {%0,%1,%2,%3};"
        : "+f"(c[0]), "+f"(c[1]), "+f"(c[2]), "+f"(c[3])
        : "r"(a[0]), "r"(a[1]), "r"(a[2]), "r"(a[3]), "r"(b[0]), "r"(b[1]));
}
__device__ __forceinline__ void mma_f16(float* c, const uint32_t* a, const uint32_t* b) {
    asm volatile(
        "mma.sync.aligned.m16n8k16.row.col.f32.f16.f16.f32 "
        "{%0,%1,%2,%3}, {%4,%5,%6,%7}, {%8,%9}, {%0,%1,%2,%3};"
        : "+f"(c[0]), "+f"(c[1]), "+f"(c[2]), "+f"(c[3])
        : "r"(a[0]), "r"(a[1]), "r"(a[2]), "r"(a[3]), "r"(b[0]), "r"(b[1]));
}
__device__ __forceinline__ void cp16(uint32_t dst, const void* src, bool p) {
    asm volatile("cp.async.cg.shared.global [%0], [%1], 16, %2;"
                 :: "r"(dst), "l"(src), "r"(p ? 16 : 0) : "memory");
}
#define CP_COMMIT() asm volatile("cp.async.commit_group;" ::: "memory")
#define CP_WAIT0()  asm volatile("cp.async.wait_group 0;" ::: "memory")
#define CP_WAIT1()  asm volatile("cp.async.wait_group 1;" ::: "memory")
#define CP_WAIT2()  asm volatile("cp.async.wait_group 2;" ::: "memory")

__device__ __forceinline__ uint32_t h2u(__half2 h) {
    return *reinterpret_cast<uint32_t*>(&h);
}

// ---------------- tile geometry ----------------
#define BK 32
// layer 1: 64 x 128 tile, 256 threads (8 warps 2x4, warp tile 32x32)
#define BM 64
#define BN 128
#define A_PADH 40                    // halfs per A row (20 u32, conflict-free)
#define A_TILEH 1280                 // u32 per A stage: 64*20
#define B_PADW 136                   // u32 per k-pair row (conflict-free)
#define B_TILEW (16 * B_PADW)        // 2176 u32 per B stage
#define NST1 3                       // A stages (cp.async)

// dense (tf32, unchanged): 32 x 64 tile, 128 threads
#define DM 32
#define DN 64
#define A_PAD 36
#define DB_PAD 68
#define DA_TILE (DM * A_PAD)
#define DB_TILE (BK * DB_PAD)
#define NSTD 3
#define D_SMEM (NSTD * (DA_TILE + DB_TILE) * 4)

// ---------------------------------------------------------------
__global__ void bucket_kernel(const int* __restrict__ orders)
{
    __shared__ int s_cnt[NEXP];
    __shared__ int s_off[NEXP];
    int b = threadIdx.x;
    if (b < NEXP) s_cnt[b] = 0;
    __syncthreads();
    int o = orders[b];
    int pos = atomicAdd(&s_cnt[o], 1);
    __syncthreads();
    if (b == 0) {
        int a = 0;
        for (int i = 0; i < NEXP; i++) { s_off[i] = a; g_cnt[i] = s_cnt[i]; g_off[i] = a; a += s_cnt[i]; }
        g_off[NEXP] = a;
    }
    __syncthreads();
    g_idx[o * BATCH + pos] = b;
    int row = s_off[o] + pos;
    g_rowb[row] = b;
    g_rowo[row] = o;
}

// ---------------------------------------------------------------
// pack X -> f16, compact rows, zero pad to k-tile boundary
// ---------------------------------------------------------------
__global__ void pack_kernel(const float* __restrict__ mazes,
                            const float* __restrict__ embed)
{
    const int r = blockIdx.x;
    const int b = g_rowb[r];
    const int o = g_rowo[r];
    const int s = c_sizes[o];
    const int Ktot = s + EMBED;
    const int kal  = (Ktot + 31) & ~31;
    const float* src = mazes + (size_t)b * S_MAX;
    __half* dst = g_xch[r];
    for (int k = threadIdx.x; k < s; k += 256) dst[k] = __float2half_rn(src[k]);
    for (int k = s + threadIdx.x; k < kal; k += 256)
        dst[k] = __float2half_rn((k < Ktot) ? embed[o * EMBED + (k - s)] : 0.f);
}

// ---------------------------------------------------------------
// Layer-1 grouped fp16 GEMM (fp32 accum), split-K.
// A: f16 [m][k] via cp.async (3-stage). B: LDG f32 -> cvt -> f16 k-pair
// [k/2][n] smem (2-stage, register-buffered).
// grid = (8 n-tiles, 16 m-tiles, 17 z), 256 threads.
// ---------------------------------------------------------------
__global__ __launch_bounds__(256)
void layer1_mma(const float* __restrict__ W_in,
                const float* __restrict__ b_in)
{
    const int z = blockIdx.z;
    const int o = c_zo[z];
    const int c = c_zc[z];
    const int cnt = g_cnt[o];
    const int m0 = blockIdx.y * BM;
    if (m0 >= cnt) return;
    const int s    = c_sizes[o];
    const int Ktot = s + EMBED;
    const int kbeg = c * KCHUNK;
    if (kbeg >= Ktot) return;
    const int kend = min(kbeg + KCHUNK, Ktot);
    const int n0   = blockIdx.x * BN;
    const int ns   = c_nsplit[o];

    __shared__ uint32_t sA[NST1 * A_TILEH];   // f16 [m][k], pitch 40 halfs
    __shared__ uint32_t sB[2 * B_TILEW];      // f16 k-pair [k/2][n], pitch 136 u32
    const uint32_t aOffB = (uint32_t)__cvta_generic_to_shared(sA);

    const int tid  = threadIdx.x;
    const int wid  = tid >> 5;
    const int lane = tid & 31;
    const int gid  = lane >> 2;
    const int tig  = lane & 3;
    const int warp_m = (wid >> 2) * 32;
    const int warp_n = (wid & 3) * 32;

    const int arow0 = g_off[o] + m0;
    const float* wexp = W_in + (size_t)o * D_IN * H4;

    // per-thread B staging coords (2 tasks)
    const int bkp[2]  = { tid >> 5, (tid + 256) >> 5 };
    const int bcol[2] = { (tid & 31) * 4, (tid & 31) * 4 };

    float acc[2][4][4];
#pragma unroll
    for (int i = 0; i < 2; i++)
#pragma unroll
        for (int j = 0; j < 4; j++)
#pragma unroll
            for (int q = 0; q < 4; q++) acc[i][j][q] = 0.f;

    const int T = (kend - kbeg + BK - 1) / BK;

    // A issue: 1 cp16 per thread (64 rows x 32 halfs = 4KB)
    auto issueA = [&](int t) {
        const int k0  = kbeg + t * BK;
        const int buf = t % NST1;
        int row = tid >> 2;
        int kc  = (tid & 3) * 8;               // halfs
        uint32_t dst = aOffB + (uint32_t)buf * A_TILEH * 4 + (uint32_t)(row * 80 + kc * 2);
        cp16(dst, &g_xch[arow0 + row][k0 + kc], true);
        CP_COMMIT();
    };

    float4 bve[2], bvo[2];
    auto ldgB = [&](int t) {
        const int k0 = kbeg + t * BK;
#pragma unroll
        for (int j = 0; j < 2; j++) {
            int ke = k0 + 2 * bkp[j];
            int ko = ke + 1;
            bve[j] = make_float4(0.f, 0.f, 0.f, 0.f);
            bvo[j] = make_float4(0.f, 0.f, 0.f, 0.f);
            if (ke < kend) {
                int wr = (ke < s) ? ke : (S_MAX + (ke - s));
                bve[j] = *(const float4*)(wexp + (size_t)wr * H4 + n0 + bcol[j]);
            }
            if (ko < kend) {
                int wr = (ko < s) ? ko : (S_MAX + (ko - s));
                bvo[j] = *(const float4*)(wexp + (size_t)wr * H4 + n0 + bcol[j]);
            }
        }
    };
    auto stsB = [&](int t) {
        const int buf = t & 1;
#pragma unroll
        for (int j = 0; j < 2; j++) {
            uint4 u;
            u.x = h2u(__floats2half2_rn(bve[j].x, bvo[j].x));
            u.y = h2u(__floats2half2_rn(bve[j].y, bvo[j].y));
            u.z = h2u(__floats2half2_rn(bve[j].z, bvo[j].z));
            u.w = h2u(__floats2half2_rn(bve[j].w, bvo[j].w));
            *(uint4*)&sB[buf * B_TILEW + bkp[j] * B_PADW + bcol[j]] = u;
        }
    };

    // preload
    ldgB(0); stsB(0);
    issueA(0);
    if (T > 1) issueA(1);

    for (int t = 0; t < T; t++) {
        if (t + 1 < T) ldgB(t + 1);
        if (t + 2 < T) { issueA(t + 2); CP_WAIT2(); }
        else if (t + 1 < T) { CP_WAIT1(); }
        else { CP_WAIT0(); }
        __syncthreads();

        const uint32_t* As = sA + (t % NST1) * A_TILEH;
        const uint32_t* Bs = sB + (t & 1) * B_TILEW;
#pragma unroll
        for (int kf = 0; kf < 2; kf++) {           // two k16 chunks
            uint32_t a[2][4];
#pragma unroll
            for (int mf = 0; mf < 2; mf++) {
                int r = warp_m + mf * 16 + gid;
                const int kb = kf * 8 + tig;       // u32 col within row
                a[mf][0] = As[r * 20 + kb];
                a[mf][1] = As[(r + 8) * 20 + kb];
                a[mf][2] = As[r * 20 + kb + 4];
                a[mf][3] = As[(r + 8) * 20 + kb + 4];
            }
            uint32_t b[4][2];
#pragma unroll
            for (int nf = 0; nf < 4; nf++) {
                int col = warp_n + nf * 8 + gid;
                b[nf][0] = Bs[(kf * 8 + tig) * B_PADW + col];
                b[nf][1] = Bs[(kf * 8 + tig + 4) * B_PADW + col];
            }
#pragma unroll
            for (int mf = 0; mf < 2; mf++)
#pragma unroll
                for (int nf = 0; nf < 4; nf++)
                    mma_f16(acc[mf][nf], a[mf], b[nf]);
        }
        if (t + 1 < T) stsB(t + 1);
        __syncthreads();
    }

    // ---- writeback ----
    const int grow0 = g_off[o] + m0;
#pragma unroll
    for (int mf = 0; mf < 2; mf++) {
#pragma unroll
        for (int h = 0; h < 2; h++) {
            int r = warp_m + mf * 16 + gid + h * 8;
            if (m0 + r < cnt) {
                if (ns == 1) {
                    float* dst = g_h + (size_t)(grow0 + r) * H4 + n0 + warp_n;
                    const float* bs = b_in + (size_t)o * H4 + n0 + warp_n;
#pragma unroll
                    for (int nf = 0; nf < 4; nf++) {
                        float x = acc[mf][nf][h * 2]     + __ldg(bs + nf * 8 + tig * 2);
                        float y = acc[mf][nf][h * 2 + 1] + __ldg(bs + nf * 8 + tig * 2 + 1);
                        x = (x > 0.f) ? x : 0.2f * x;
                        y = (y > 0.f) ? y : 0.2f * y;
                        *(float2*)(dst + nf * 8 + tig * 2) = make_float2(x, y);
                    }
                } else {
                    float* dst = &g_hpart[c][grow0 + r][n0 + warp_n];
#pragma unroll
                    for (int nf = 0; nf < 4; nf++)
                        *(float2*)(dst + nf * 8 + tig * 2) =
                            make_float2(acc[mf][nf][h * 2], acc[mf][nf][h * 2 + 1]);
                }
            }
        }
    }
}

// ---------------------------------------------------------------
// Layer-1 epilogue: only multi-split experts (5,6), unrolled.
// ---------------------------------------------------------------
__global__ void l1_epilogue(const float* __restrict__ b_in)
{
    const int r  = blockIdx.x;
    const int o  = g_rowo[r];
    const int ns = c_nsplit[o];
    if (ns == 1) return;
    const int j  = threadIdx.x * 4;
    float4 v = *(const float4*)(b_in + (size_t)o * H4 + j);
    if (ns == 3) {
#pragma unroll
        for (int cc = 0; cc < 3; cc++) {
            float4 p = *(const float4*)(&g_hpart[cc][r][j]);
            v.x += p.x; v.y += p.y; v.z += p.z; v.w += p.w;
        }
    } else {
#pragma unroll
        for (int cc = 0; cc < 9; cc++) {
            float4 p = *(const float4*)(&g_hpart[cc][r][j]);
            v.x += p.x; v.y += p.y; v.z += p.z; v.w += p.w;
        }
    }
    v.x = (v.x > 0.f) ? v.x : 0.2f * v.x;
    v.y = (v.y > 0.f) ? v.y : 0.2f * v.y;
    v.z = (v.z > 0.f) ? v.z : 0.2f * v.z;
    v.w = (v.w > 0.f) ? v.w : 0.2f * v.w;
    *(float4*)(g_h + (size_t)r * H4 + j) = v;
}

// ---------------------------------------------------------------
// Dense tf32 GEMM + bias + leaky, 32x64 tiles, 128 thr, 3-stage.
// ---------------------------------------------------------------
__global__ __launch_bounds__(128)
void dense_mma(const float* __restrict__ B, const float* __restrict__ bias,
               int K, int N, int sel)
{
    const float* A = (sel == 0) ? g_h  : g_z1;
    float*       C = (sel == 0) ? g_z1 : g_z2;
    const int m0 = blockIdx.y * DM;
    const int n0 = blockIdx.x * DN;

    extern __shared__ uint32_t sm[];
    uint32_t* sA = sm;
    uint32_t* sB = sm + NSTD * DA_TILE;
    const uint32_t aOffB = (uint32_t)__cvta_generic_to_shared(sA);
    const uint32_t bOffB = (uint32_t)__cvta_generic_to_shared(sB);

    const int tid  = threadIdx.x;
    const int wid  = tid >> 5;
    const int lane = tid & 31;
    const int gid  = lane >> 2;
    const int tig  = lane & 3;
    const int warp_n = wid * 16;

    float acc[2][2][4];
#pragma unroll
    for (int i = 0; i < 2; i++)
#pragma unroll
        for (int j = 0; j < 2; j++)
#pragma unroll
            for (int q = 0; q < 4; q++) acc[i][j][q] = 0.f;

    auto issue = [&](int t) {
        const int k0  = t * BK;
        const int buf = t % NSTD;
#pragma unroll
        for (int j = 0; j < 2; j++) {
            int cch = tid + j * 128;
            int row = cch >> 3;
            int kc  = (cch & 7) * 4;
            uint32_t dst = aOffB + (uint32_t)(buf * DA_TILE + row * A_PAD + kc) * 4;
            cp16(dst, A + (size_t)(m0 + row) * K + k0 + kc, true);
        }
#pragma unroll
        for (int j = 0; j < 4; j++) {
            int cch = tid + j * 128;
            int kk  = cch >> 4;
            int col = (cch & 15) * 4;
            uint32_t dst = bOffB + (uint32_t)(buf * DB_TILE + kk * DB_PAD + col) * 4;
            cp16(dst, B + (size_t)(k0 + kk) * N + n0 + col, true);
        }
        CP_COMMIT();
    };

    const int T = K / BK;
    issue(0);
    if (T > 1) issue(1);
    for (int t = 0; t < T; t++) {
        if (t + 2 < T) { issue(t + 2); CP_WAIT2(); }
        else if (t + 1 < T) { CP_WAIT1(); }
        else { CP_WAIT0(); }
        __syncthreads();

        const uint32_t* As = sA + (t % NSTD) * DA_TILE;
        const uint32_t* Bs = sB + (t % NSTD) * DB_TILE;
#pragma unroll
        for (int kf = 0; kf < 4; kf++) {
            uint32_t a[2][4];
#pragma unroll
            for (int mf = 0; mf < 2; mf++) {
                int r = mf * 16 + gid;
                a[mf][0] = As[r * A_PAD + kf * 8 + tig];
                a[mf][1] = As[(r + 8) * A_PAD + kf * 8 + tig];
                a[mf][2] = As[r * A_PAD + kf * 8 + tig + 4];
                a[mf][3] = As[(r + 8) * A_PAD + kf * 8 + tig + 4];
            }
            uint32_t b[2][2];
#pragma unroll
            for (int nf = 0; nf < 2; nf++) {
                int col = warp_n + nf * 8 + gid;
                b[nf][0] = Bs[(kf * 8 + tig) * DB_PAD + col];
                b[nf][1] = Bs[(kf * 8 + tig + 4) * DB_PAD + col];
            }
#pragma unroll
            for (int mf = 0; mf < 2; mf++)
#pragma unroll
                for (int nf = 0; nf < 2; nf++)
                    mma_tf32(acc[mf][nf], a[mf], b[nf]);
        }
        __syncthreads();
    }

#pragma unroll
    for (int mf = 0; mf < 2; mf++) {
#pragma unroll
        for (int h = 0; h < 2; h++) {
            int m = m0 + mf * 16 + gid + h * 8;
            float* dst = C + (size_t)m * N + n0 + warp_n;
            const float* bs = bias + n0 + warp_n;
#pragma unroll
            for (int nf = 0; nf < 2; nf++) {
                float x = acc[mf][nf][h * 2]     + __ldg(bs + nf * 8 + tig * 2);
                float y = acc[mf][nf][h * 2 + 1] + __ldg(bs + nf * 8 + tig * 2 + 1);
                x = (x > 0.f) ? x : 0.2f * x;
                y = (y > 0.f) ? y : 0.2f * y;
                *(float2*)(dst + nf * 8 + tig * 2) = make_float2(x, y);
            }
        }
    }
}

// ---------------------------------------------------------------
// Final 256->1 GEMV + sigmoid, scatter to original batch order.
// ---------------------------------------------------------------
__global__ void l4_kernel(const float* __restrict__ W3,
                          const float* __restrict__ b3,
                          float* __restrict__ out)
{
    const int warp = threadIdx.x >> 5;
    const int lane = threadIdx.x & 31;
    const int r = blockIdx.x * 8 + warp;
    const float* zv = g_z2 + (size_t)r * H1;
    float p = 0.f;
#pragma unroll
    for (int l = 0; l < 8; l++) p += zv[lane + l * 32] * W3[lane + l * 32];
#pragma unroll
    for (int d = 16; d; d >>= 1) p += __shfl_xor_sync(0xffffffffu, p, d);
    if (lane == 0) {
        float x = p + b3[0];
        out[g_rowb[r]] = 1.f / (1.f + expf(-x));
    }
}

// ---------------------------------------------------------------
extern "C" void kernel_launch(void* const* d_in, const int* in_sizes, int n_in,
                              void* d_out, int out_size)
{
    const float* mazes  = (const float*)d_in[0];
    const int*   orders = (const int*)  d_in[1];
    const float* embed  = (const float*)d_in[2];
    const float* W_in   = (const float*)d_in[3];
    const float* b_in   = (const float*)d_in[4];
    const float* W1     = (const float*)d_in[5];
    const float* b1     = (const float*)d_in[6];
    const float* W2     = (const float*)d_in[7];
    const float* b2     = (const float*)d_in[8];
    const float* W3     = (const float*)d_in[9];
    const float* b3     = (const float*)d_in[10];
    float* out = (float*)d_out;

    cudaFuncSetAttribute(dense_mma, cudaFuncAttributeMaxDynamicSharedMemorySize, D_SMEM);

    bucket_kernel<<<1, BATCH>>>(orders);
    pack_kernel<<<BATCH, 256>>>(mazes, embed);
    layer1_mma<<<dim3(H4 / BN, BATCH / BM, NZ), 256>>>(W_in, b_in);
    l1_epilogue<<<BATCH, 256>>>(b_in);
    dense_mma<<<dim3(H2 / DN, BATCH / DM), 128, D_SMEM>>>(W1, b1, H4, H2, 0);
    dense_mma<<<dim3(H1 / DN, BATCH / DM), 128, D_SMEM>>>(W2, b2, H2, H1, 1);
    l4_kernel<<<BATCH / 8, 256>>>(W3, b3, out);
}